// round 6
// baseline (speedup 1.0000x reference)
#include <cuda_runtime.h>
#include <math.h>
#include <stdint.h>

#define IN_DIM 128
#define NHEAD 4
#define HDIM 32
#define MAX_ROWS 51200
#define MAX_E 1050000
#define SA 132   // smem stride activation tiles
#define SW 136   // smem stride weight tiles

__device__ __align__(16) float g_alpha[MAX_ROWS * NHEAD]; // [n][h]
__device__ __align__(16) float g_xv[MAX_ROWS * IN_DIM];   // [n][d*4+h]
__device__ __align__(16) float g_S1[MAX_ROWS * IN_DIM];   // pre-MLP features
__device__ int g_esrcA[MAX_E];
__device__ int g_esrcB[MAX_E];
__device__ int g_offA[MAX_ROWS + 1];
__device__ int g_offB[MAX_ROWS + 1];
__device__ int g_cnt[MAX_ROWS + 1];
__device__ int g_cur[MAX_ROWS + 1];
__device__ int g_scst[64];   // lookback states: (value<<2)|status

__device__ __forceinline__ float warp_sum(float v) {
    #pragma unroll
    for (int off = 16; off; off >>= 1) v += __shfl_xor_sync(0xffffffffu, v, off);
    return v;
}

__device__ __forceinline__ float to_tf32(float x) {
    uint32_t u;
    asm("cvt.rna.tf32.f32 %0, %1;" : "=r"(u) : "f"(x));
    return __uint_as_float(u);
}

__device__ __forceinline__ void mma_tile(float c[4], const uint32_t a[4],
                                         uint32_t b0, uint32_t b1) {
    asm volatile(
        "mma.sync.aligned.m16n8k8.row.col.f32.tf32.tf32.f32 "
        "{%0,%1,%2,%3}, {%4,%5,%6,%7}, {%8,%9}, {%0,%1,%2,%3};"
        : "+f"(c[0]), "+f"(c[1]), "+f"(c[2]), "+f"(c[3])
        : "r"(a[0]), "r"(a[1]), "r"(a[2]), "r"(a[3]), "r"(b0), "r"(b1));
}

// 64x128x128 GEMM on smem tiles. 8 warps: wm = wid&1 (32 rows), wn = wid>>1 (32 cols).
__device__ __forceinline__ void gemm_core64(const float* __restrict__ shA,
                                            const float* __restrict__ shB,
                                            float acc[2][4][4],
                                            int wm, int wn, int lane) {
    int g = lane >> 2, t = lane & 3;
    #pragma unroll 2
    for (int k0 = 0; k0 < 128; k0 += 8) {
        uint32_t a[2][4];
        #pragma unroll
        for (int mi = 0; mi < 2; mi++) {
            const float* p = shA + (wm * 32 + mi * 16 + g) * SA + k0 + t;
            a[mi][0] = __float_as_uint(p[0]);
            a[mi][1] = __float_as_uint(p[8 * SA]);
            a[mi][2] = __float_as_uint(p[4]);
            a[mi][3] = __float_as_uint(p[8 * SA + 4]);
        }
        #pragma unroll
        for (int ni = 0; ni < 4; ni++) {
            const float* q = shB + (k0 + t) * SW + wn * 32 + ni * 8 + g;
            uint32_t b0 = __float_as_uint(q[0]);
            uint32_t b1 = __float_as_uint(q[4 * SW]);
            mma_tile(acc[0][ni], a[0], b0, b1);
            mma_tile(acc[1][ni], a[1], b0, b1);
        }
    }
}

// ---------------------------------------------------------------------------
// Fused: kq = K@Q (per-CTA), xv = x @ V_cat (tf32 MMA), alpha = x . kq.
__global__ void __launch_bounds__(256, 2)
gemm_xv(const float* __restrict__ x, const float* __restrict__ V,
        const float* __restrict__ K, const float* __restrict__ Q, int nrows) {
    extern __shared__ float sm[];
    float* ws = sm;                     // [c][d*4+h], stride SW
    float* xs = sm + 128 * SW;          // [r][c], stride SA (also C staging)
    float* kq_s = sm + 128 * SW + 64 * SA;  // [h*132 + c]
    int tid = threadIdx.x;
    int row0 = blockIdx.x * 64;
    int lane = tid & 31, wid = tid >> 5;
    int wm = wid & 1, wn = wid >> 1;

    // kq: 512 dots of 32
    #pragma unroll
    for (int idx = tid; idx < 512; idx += 256) {
        int h = idx >> 7, c = idx & 127;
        float s = 0.f;
        #pragma unroll
        for (int d = 0; d < HDIM; d++)
            s += K[h * (IN_DIM * HDIM) + c * HDIM + d] * Q[h * HDIM + d];
        kq_s[h * 132 + c] = s;
    }
    for (int idx = tid; idx < 16384; idx += 256) {   // V linear: h,c,d
        int h = idx >> 12, c = (idx >> 5) & 127, d = idx & 31;
        ws[c * SW + d * 4 + h] = to_tf32(V[idx]);
    }
    for (int idx = tid; idx < 2048; idx += 256) {
        int r = idx >> 5, q = idx & 31;
        int row = row0 + r;
        float4 v = (row < nrows) ? *(const float4*)&x[(size_t)row * 128 + q * 4]
                                 : make_float4(0.f, 0.f, 0.f, 0.f);
        xs[r * SA + q * 4 + 0] = to_tf32(v.x);
        xs[r * SA + q * 4 + 1] = to_tf32(v.y);
        xs[r * SA + q * 4 + 2] = to_tf32(v.z);
        xs[r * SA + q * 4 + 3] = to_tf32(v.w);
    }
    __syncthreads();

    float acc[2][4][4];
    #pragma unroll
    for (int i = 0; i < 2; i++)
        #pragma unroll
        for (int j = 0; j < 4; j++)
            #pragma unroll
            for (int k = 0; k < 4; k++) acc[i][j][k] = 0.f;
    gemm_core64(xs, ws, acc, wm, wn, lane);

    // alpha from xs (still intact): row = tid>>2, h = tid&3
    {
        int r = tid >> 2, h = tid & 3;
        float s = 0.f;
        const float* xr = &xs[r * SA];
        const float* kr = &kq_s[h * 132];
        #pragma unroll 4
        for (int c = 0; c < 128; c++) s += xr[c] * kr[c];
        int row = row0 + r;
        if (row < nrows) g_alpha[(size_t)row * 4 + h] = s;
    }
    __syncthreads();   // all xs reads done

    int g = lane >> 2, t = lane & 3;
    #pragma unroll
    for (int mi = 0; mi < 2; mi++)
        #pragma unroll
        for (int ni = 0; ni < 4; ni++) {
            int r = wm * 32 + mi * 16 + g;
            int c = wn * 32 + ni * 8 + 2 * t;
            *(float2*)&xs[r * SA + c] = make_float2(acc[mi][ni][0], acc[mi][ni][1]);
            *(float2*)&xs[(r + 8) * SA + c] = make_float2(acc[mi][ni][2], acc[mi][ni][3]);
        }
    __syncthreads();

    for (int idx = tid; idx < 2048; idx += 256) {
        int r = idx >> 5, q = idx & 31;
        int row = row0 + r;
        if (row < nrows)
            *(float4*)&g_xv[(size_t)row * 128 + q * 4] = *(float4*)&xs[r * SA + q * 4];
    }
}

// ---------------------------------------------------------------------------
__global__ void hist_kernel(const int* __restrict__ tgt, int E) {
    if (blockIdx.x == 0 && threadIdx.x < 64) g_scst[threadIdx.x] = 0;
    int stride = gridDim.x * blockDim.x;
    int gid = blockIdx.x * blockDim.x + threadIdx.x;
    int n4 = E >> 2;
    const int4* t4 = (const int4*)tgt;
    for (int i = gid; i < n4; i += stride) {
        int4 t = t4[i];
        atomicAdd(&g_cnt[t.x], 1);
        atomicAdd(&g_cnt[t.y], 1);
        atomicAdd(&g_cnt[t.z], 1);
        atomicAdd(&g_cnt[t.w], 1);
    }
    for (int e = n4 * 4 + gid; e < E; e += stride) atomicAdd(&g_cnt[tgt[e]], 1);
}

// single-launch exclusive scan with decoupled lookback (grid <= 50 blocks)
__global__ void scan_kernel(int n, int* __restrict__ off) {
    __shared__ int wsum[32];
    __shared__ int s_excl;
    int tid = threadIdx.x, lane = tid & 31, wid = tid >> 5;
    int bid = blockIdx.x;
    int i = bid * 1024 + tid;
    int v = (i < n) ? g_cnt[i] : 0;
    int x = v;
    #pragma unroll
    for (int o = 1; o < 32; o <<= 1) {
        int t = __shfl_up_sync(0xffffffffu, x, o);
        if (lane >= o) x += t;
    }
    if (lane == 31) wsum[wid] = x;
    __syncthreads();
    if (wid == 0) {
        int s = wsum[lane];
        #pragma unroll
        for (int o = 1; o < 32; o <<= 1) {
            int t = __shfl_up_sync(0xffffffffu, s, o);
            if (lane >= o) s += t;
        }
        wsum[lane] = s;
    }
    __syncthreads();
    int base = (wid > 0) ? wsum[wid - 1] : 0;
    int incl = base + x;
    int local_total = wsum[31];

    if (tid == 0) {
        int run = 0;
        if (bid > 0) {
            atomicExch(&g_scst[bid], (local_total << 2) | 1);
            int j = bid - 1;
            while (j >= 0) {
                int st = atomicAdd(&g_scst[j], 0);
                int tag = st & 3;
                if (tag == 2) { run += st >> 2; break; }
                if (tag == 1) { run += st >> 2; j--; }
            }
        }
        atomicExch(&g_scst[bid], ((run + local_total) << 2) | 2);
        s_excl = run;
    }
    __syncthreads();
    int e = s_excl + incl - v;
    if (i < n) { off[i] = e; g_cur[i] = e; }
    if (bid == gridDim.x - 1 && tid == 1023) off[n] = s_excl + local_total;
}

// topology-only scatter
__global__ void scatter_kernel(const int* __restrict__ tgt,
                               const int* __restrict__ src,
                               int* __restrict__ esrc, int E) {
    int stride = gridDim.x * blockDim.x;
    int gid = blockIdx.x * blockDim.x + threadIdx.x;
    int n4 = E >> 2;
    const int4* t4 = (const int4*)tgt;
    const int4* s4 = (const int4*)src;
    for (int i = gid; i < n4; i += stride) {
        int4 t = t4[i]; int4 s = s4[i];
        int p;
        p = atomicAdd(&g_cur[t.x], 1); esrc[p] = s.x;
        p = atomicAdd(&g_cur[t.y], 1); esrc[p] = s.y;
        p = atomicAdd(&g_cur[t.z], 1); esrc[p] = s.z;
        p = atomicAdd(&g_cur[t.w], 1); esrc[p] = s.w;
    }
    for (int e = n4 * 4 + gid; e < E; e += stride) {
        int p = atomicAdd(&g_cur[tgt[e]], 1); esrc[p] = src[e];
    }
}

// ---------------------------------------------------------------------------
__global__ void __launch_bounds__(256)
segagg_kernel(const int* __restrict__ esrc, const int* __restrict__ off,
              const float* __restrict__ qbias, int n_tgt) {
    __shared__ int    sh_sn[256];
    __shared__ float4 sh_w[256];
    int wid = threadIdx.x >> 5, lane = threadIdx.x & 31;
    int gw = blockIdx.x * 8 + wid;
    if (gw >= n_tgt) return;
    int start = off[gw], end = off[gw + 1];
    float* outrow = &g_S1[(size_t)gw * 128];

    if (end == start) {
        #pragma unroll
        for (int k = 0; k < 4; k++) outrow[k * 32 + lane] = qbias[k * 32 + lane];
        return;
    }

    float m[4], s[4];
    #pragma unroll
    for (int k = 0; k < 4; k++) { m[k] = -1e30f; s[k] = 0.f; }
    for (int i = start + lane; i < end; i += 32) {
        int sn = __ldg(&esrc[i]);
        float4 a4 = *(const float4*)&g_alpha[(size_t)sn * 4];
        float a[4] = {a4.x, a4.y, a4.z, a4.w};
        #pragma unroll
        for (int k = 0; k < 4; k++) {
            if (a[k] > m[k]) { s[k] = s[k] * __expf(m[k] - a[k]) + 1.f; m[k] = a[k]; }
            else             { s[k] += __expf(a[k] - m[k]); }
        }
    }
    #pragma unroll
    for (int offx = 16; offx; offx >>= 1) {
        #pragma unroll
        for (int k = 0; k < 4; k++) {
            float mo = __shfl_xor_sync(0xffffffffu, m[k], offx);
            float so = __shfl_xor_sync(0xffffffffu, s[k], offx);
            float mn = fmaxf(m[k], mo);
            s[k] = s[k] * __expf(m[k] - mn) + so * __expf(mo - mn);
            m[k] = mn;
        }
    }
    float inv[4];
    #pragma unroll
    for (int k = 0; k < 4; k++) inv[k] = 1.0f / s[k];

    int sbase = wid * 32;
    float acc[4] = {0.f, 0.f, 0.f, 0.f};
    for (int i0 = start; i0 < end; i0 += 32) {
        int cnt = end - i0; if (cnt > 32) cnt = 32;
        if (lane < cnt) {
            int sn = __ldg(&esrc[i0 + lane]);
            float4 a4 = *(const float4*)&g_alpha[(size_t)sn * 4];
            sh_sn[sbase + lane] = sn;
            sh_w[sbase + lane] = make_float4(__expf(a4.x - m[0]) * inv[0],
                                            __expf(a4.y - m[1]) * inv[1],
                                            __expf(a4.z - m[2]) * inv[2],
                                            __expf(a4.w - m[3]) * inv[3]);
        }
        __syncwarp();
        #pragma unroll 4
        for (int j = 0; j < cnt; j++) {
            int sn = sh_sn[sbase + j];
            float4 wv = sh_w[sbase + j];
            float4 v = *(const float4*)&g_xv[(size_t)sn * 128 + lane * 4];
            acc[0] += wv.x * v.x; acc[1] += wv.y * v.y;
            acc[2] += wv.z * v.z; acc[3] += wv.w * v.w;
        }
        __syncwarp();
    }
    #pragma unroll
    for (int k = 0; k < 4; k++)
        outrow[k * 32 + lane] = acc[k] + qbias[k * 32 + lane];
}

// ---------------------------------------------------------------------------
// 64-row MLP, 2 CTAs/SM. One activation buffer (h -> t -> residual),
// residual h values held in registers at C-fragment positions.
__global__ void __launch_bounds__(256, 2)
mlp_kernel(const float* __restrict__ g0, const float* __restrict__ b0,
           const float* __restrict__ W1, const float* __restrict__ W2,
           const float* __restrict__ g1, const float* __restrict__ b1,
           float* __restrict__ out, int nrows) {
    extern __shared__ float sm[];
    float* sh_a = sm;                 // [64][SA]
    float* sh_w = sm + 64 * SA;       // [128][SW]
    int tid = threadIdx.x;
    int row0 = blockIdx.x * 64;
    int wid = tid >> 5, lane = tid & 31;
    int wm = wid & 1, wn = wid >> 1;
    int g = lane >> 2, t = lane & 3;

    for (int idx = tid; idx < 2048; idx += 256) {
        int r = idx >> 5, q = idx & 31;
        int row = row0 + r;
        float4 v = (row < nrows) ? *(const float4*)&g_S1[(size_t)row * 128 + q * 4]
                                 : make_float4(0.f, 0.f, 0.f, 0.f);
        *(float4*)&sh_a[r * SA + q * 4] = v;
    }
    for (int idx = tid; idx < 4096; idx += 256) {
        float4 v = *(const float4*)&W1[idx * 4];
        int r = idx >> 5, q = idx & 31;
        sh_w[r * SW + q * 4 + 0] = to_tf32(v.x);
        sh_w[r * SW + q * 4 + 1] = to_tf32(v.y);
        sh_w[r * SW + q * 4 + 2] = to_tf32(v.z);
        sh_w[r * SW + q * 4 + 3] = to_tf32(v.w);
    }
    __syncthreads();

    // LN0 in place (tf32 out)
    float4 gA = *(const float4*)&g0[lane * 4];
    float4 bA = *(const float4*)&b0[lane * 4];
    for (int r = wid; r < 64; r += 8) {
        float4 v = *(float4*)&sh_a[r * SA + lane * 4];
        float mean = warp_sum(v.x + v.y + v.z + v.w) * (1.f / 128.f);
        float dx = v.x - mean, dy = v.y - mean, dz = v.z - mean, dw = v.w - mean;
        float var = warp_sum(dx * dx + dy * dy + dz * dz + dw * dw) * (1.f / 128.f);
        float rstd = rsqrtf(var + 1e-5f);
        sh_a[r * SA + lane * 4 + 0] = to_tf32(dx * rstd * gA.x + bA.x);
        sh_a[r * SA + lane * 4 + 1] = to_tf32(dy * rstd * gA.y + bA.y);
        sh_a[r * SA + lane * 4 + 2] = to_tf32(dz * rstd * gA.z + bA.z);
        sh_a[r * SA + lane * 4 + 3] = to_tf32(dw * rstd * gA.w + bA.w);
    }
    __syncthreads();

    float acc[2][4][4];
    #pragma unroll
    for (int i = 0; i < 2; i++)
        #pragma unroll
        for (int j = 0; j < 4; j++)
            #pragma unroll
            for (int k = 0; k < 4; k++) acc[i][j][k] = 0.f;
    gemm_core64(sh_a, sh_w, acc, wm, wn, lane);

    // stash residual h at this thread's C positions
    float hres[2][4][4];
    #pragma unroll
    for (int mi = 0; mi < 2; mi++)
        #pragma unroll
        for (int ni = 0; ni < 4; ni++) {
            int r = wm * 32 + mi * 16 + g;
            int c = wn * 32 + ni * 8 + 2 * t;
            hres[mi][ni][0] = sh_a[r * SA + c];
            hres[mi][ni][1] = sh_a[r * SA + c + 1];
            hres[mi][ni][2] = sh_a[(r + 8) * SA + c];
            hres[mi][ni][3] = sh_a[(r + 8) * SA + c + 1];
        }
    __syncthreads();   // all GEMM1/hres reads done

    // t = relu(acc) -> sh_a ; W2 -> sh_w
    #pragma unroll
    for (int mi = 0; mi < 2; mi++)
        #pragma unroll
        for (int ni = 0; ni < 4; ni++) {
            int r = wm * 32 + mi * 16 + g;
            int c = wn * 32 + ni * 8 + 2 * t;
            sh_a[r * SA + c]           = to_tf32(fmaxf(acc[mi][ni][0], 0.f));
            sh_a[r * SA + c + 1]       = to_tf32(fmaxf(acc[mi][ni][1], 0.f));
            sh_a[(r + 8) * SA + c]     = to_tf32(fmaxf(acc[mi][ni][2], 0.f));
            sh_a[(r + 8) * SA + c + 1] = to_tf32(fmaxf(acc[mi][ni][3], 0.f));
        }
    for (int idx = tid; idx < 4096; idx += 256) {
        float4 v = *(const float4*)&W2[idx * 4];
        int r = idx >> 5, q = idx & 31;
        sh_w[r * SW + q * 4 + 0] = to_tf32(v.x);
        sh_w[r * SW + q * 4 + 1] = to_tf32(v.y);
        sh_w[r * SW + q * 4 + 2] = to_tf32(v.z);
        sh_w[r * SW + q * 4 + 3] = to_tf32(v.w);
    }
    __syncthreads();

    #pragma unroll
    for (int i = 0; i < 2; i++)
        #pragma unroll
        for (int j = 0; j < 4; j++)
            #pragma unroll
            for (int k = 0; k < 4; k++) acc[i][j][k] = 0.f;
    gemm_core64(sh_a, sh_w, acc, wm, wn, lane);
    __syncthreads();   // GEMM2 reads done before residual overwrite

    #pragma unroll
    for (int mi = 0; mi < 2; mi++)
        #pragma unroll
        for (int ni = 0; ni < 4; ni++) {
            int r = wm * 32 + mi * 16 + g;
            int c = wn * 32 + ni * 8 + 2 * t;
            sh_a[r * SA + c]           = hres[mi][ni][0] + fmaxf(acc[mi][ni][0], 0.f);
            sh_a[r * SA + c + 1]       = hres[mi][ni][1] + fmaxf(acc[mi][ni][1], 0.f);
            sh_a[(r + 8) * SA + c]     = hres[mi][ni][2] + fmaxf(acc[mi][ni][2], 0.f);
            sh_a[(r + 8) * SA + c + 1] = hres[mi][ni][3] + fmaxf(acc[mi][ni][3], 0.f);
        }
    __syncthreads();

    float4 gB = *(const float4*)&g1[lane * 4];
    float4 bB = *(const float4*)&b1[lane * 4];
    for (int r = wid; r < 64; r += 8) {
        float4 v = *(float4*)&sh_a[r * SA + lane * 4];
        float mean = warp_sum(v.x + v.y + v.z + v.w) * (1.f / 128.f);
        float dx = v.x - mean, dy = v.y - mean, dz = v.z - mean, dw = v.w - mean;
        float var = warp_sum(dx * dx + dy * dy + dz * dz + dw * dw) * (1.f / 128.f);
        float rstd = rsqrtf(var + 1e-5f);
        int row = row0 + r;
        if (row < nrows) {
            *(float4*)&out[(size_t)row * 128 + lane * 4] =
                make_float4(fmaxf(dx * rstd * gB.x + bB.x, 0.f),
                            fmaxf(dy * rstd * gB.y + bB.y, 0.f),
                            fmaxf(dz * rstd * gB.z + bB.z, 0.f),
                            fmaxf(dw * rstd * gB.w + bB.w, 0.f));
        }
    }
}

// ---------------------------------------------------------------------------
extern "C" void kernel_launch(void* const* d_in, const int* in_sizes, int n_in,
                              void* d_out, int out_size) {
    const int N = in_sizes[0] / IN_DIM;
    const int E = in_sizes[1];
    const int M = out_size / IN_DIM - N;

    const int wi = n_in - 18;
    const float* x0 = (const float*)d_in[0];
    const int* node_idx  = (const int*)d_in[1];
    const int* hedge_idx = (const int*)d_in[2];
    const float* w[18];
    for (int i = 0; i < 18; i++) w[i] = (const float*)d_in[wi + i];

    float* out = (float*)d_out;            // x_0_out [N,128]
    float* x1  = out + (size_t)N * IN_DIM; // x_1     [M,128]

    const int gemmSmem = (128 * SW + 64 * SA + 544) * 4;   // ~105.7 KB
    const int mlpSmem  = (64 * SA + 128 * SW) * 4;         // ~103.4 KB

    static int s_init = 0;
    static cudaStream_t s2;
    static cudaEvent_t evFork, evA, evB;
    static void *cnt_ptr, *offA_ptr, *offB_ptr, *esrcA_ptr, *esrcB_ptr;
    if (!s_init) {
        cudaFuncSetAttribute(gemm_xv,
                             cudaFuncAttributeMaxDynamicSharedMemorySize, gemmSmem);
        cudaFuncSetAttribute(mlp_kernel,
                             cudaFuncAttributeMaxDynamicSharedMemorySize, mlpSmem);
        cudaStreamCreateWithFlags(&s2, cudaStreamNonBlocking);
        cudaEventCreateWithFlags(&evFork, cudaEventDisableTiming);
        cudaEventCreateWithFlags(&evA, cudaEventDisableTiming);
        cudaEventCreateWithFlags(&evB, cudaEventDisableTiming);
        cudaGetSymbolAddress(&cnt_ptr, g_cnt);
        cudaGetSymbolAddress(&offA_ptr, g_offA);
        cudaGetSymbolAddress(&offB_ptr, g_offB);
        cudaGetSymbolAddress(&esrcA_ptr, g_esrcA);
        cudaGetSymbolAddress(&esrcB_ptr, g_esrcB);
        s_init = 1;
    }
    int* offA = (int*)offA_ptr;
    int* offB = (int*)offB_ptr;
    int* esrcA = (int*)esrcA_ptr;
    int* esrcB = (int*)esrcB_ptr;

    const int nbM = (M + 1023) / 1024, nbN = (N + 1023) / 1024;

    cudaEventRecord(evFork, 0);
    cudaStreamWaitEvent(s2, evFork, 0);

    // s2: CSR A (targets = hyperedges)
    cudaMemsetAsync(cnt_ptr, 0, sizeof(int) * (M + 1), s2);
    hist_kernel<<<512, 256, 0, s2>>>(hedge_idx, E);
    scan_kernel<<<nbM, 1024, 0, s2>>>(M, offA);
    scatter_kernel<<<512, 256, 0, s2>>>(hedge_idx, node_idx, esrcA, E);
    cudaEventRecord(evA, s2);
    // s2: CSR B (targets = nodes)
    cudaMemsetAsync(cnt_ptr, 0, sizeof(int) * (N + 1), s2);
    hist_kernel<<<512, 256, 0, s2>>>(node_idx, E);
    scan_kernel<<<nbN, 1024, 0, s2>>>(N, offB);
    scatter_kernel<<<512, 256, 0, s2>>>(node_idx, hedge_idx, esrcB, E);
    cudaEventRecord(evB, s2);

    // stream 0: phase 1 (v2e)
    gemm_xv<<<(N + 63) / 64, 256, gemmSmem>>>(x0, w[2], w[0], w[1], N);
    cudaStreamWaitEvent(0, evA, 0);
    segagg_kernel<<<(M + 7) / 8, 256>>>(esrcA, offA, w[1], M);
    mlp_kernel<<<(M + 63) / 64, 256, mlpSmem>>>(w[3], w[4], w[5], w[6], w[7],
                                                w[8], x1, M);
    // phase 2 (e2v)
    gemm_xv<<<(M + 63) / 64, 256, gemmSmem>>>(x1, w[11], w[9], w[10], M);
    cudaStreamWaitEvent(0, evB, 0);
    segagg_kernel<<<(N + 7) / 8, 256>>>(esrcB, offB, w[10], N);
    mlp_kernel<<<(N + 63) / 64, 256, mlpSmem>>>(w[12], w[13], w[14], w[15],
                                                w[16], w[17], out, N);
}

// round 7
// speedup vs baseline: 1.0785x; 1.0785x over previous
#include <cuda_runtime.h>
#include <math.h>
#include <stdint.h>

#define IN_DIM 128
#define NHEAD 4
#define HDIM 32
#define MAX_ROWS 51200
#define MAX_E 1050000
#define SA 132   // smem stride activation tiles
#define SW 136   // smem stride weight tiles

__device__ __align__(16) float g_kq[NHEAD * IN_DIM];      // [h][c]
__device__ __align__(16) float g_alpha[MAX_ROWS * NHEAD]; // [n][h] alpha, then p=exp(alpha-gm)
__device__ __align__(16) float g_xv[MAX_ROWS * IN_DIM];   // [n][d*4+h]
__device__ __align__(16) float g_S1[MAX_ROWS * IN_DIM];   // pre-MLP features
__device__ int g_esrcA[MAX_E];
__device__ int g_esrcB[MAX_E];
__device__ int g_offA[MAX_ROWS + 1];
__device__ int g_offB[MAX_ROWS + 1];
__device__ int g_cnt[MAX_ROWS + 1];
__device__ int g_cur[MAX_ROWS + 1];
__device__ int g_scst[64];                 // lookback states
__device__ unsigned int g_amax[4];         // per-head max, ordered-uint encoded

__device__ __forceinline__ float warp_sum(float v) {
    #pragma unroll
    for (int off = 16; off; off >>= 1) v += __shfl_xor_sync(0xffffffffu, v, off);
    return v;
}

__device__ __forceinline__ unsigned int ord_enc(float f) {
    unsigned int u = __float_as_uint(f);
    return u ^ ((unsigned int)((int)u >> 31) | 0x80000000u);
}
__device__ __forceinline__ float ord_dec(unsigned int u) {
    return __uint_as_float(u ^ ((unsigned int)((int)(~u) >> 31) | 0x80000000u));
}

__device__ __forceinline__ float to_tf32(float x) {
    uint32_t u;
    asm("cvt.rna.tf32.f32 %0, %1;" : "=r"(u) : "f"(x));
    return __uint_as_float(u);
}

__device__ __forceinline__ void mma_tile(float c[4], const uint32_t a[4],
                                         uint32_t b0, uint32_t b1) {
    asm volatile(
        "mma.sync.aligned.m16n8k8.row.col.f32.tf32.tf32.f32 "
        "{%0,%1,%2,%3}, {%4,%5,%6,%7}, {%8,%9}, {%0,%1,%2,%3};"
        : "+f"(c[0]), "+f"(c[1]), "+f"(c[2]), "+f"(c[3])
        : "r"(a[0]), "r"(a[1]), "r"(a[2]), "r"(a[3]), "r"(b0), "r"(b1));
}

// 128x128x128 GEMM on smem tiles. warp (wm 0..3, wn 0..1).
__device__ __forceinline__ void gemm_core(const float* __restrict__ shA,
                                          const float* __restrict__ shB,
                                          float acc[2][8][4],
                                          int wm, int wn, int lane) {
    int g = lane >> 2, t = lane & 3;
    #pragma unroll 2
    for (int k0 = 0; k0 < 128; k0 += 8) {
        uint32_t a[2][4];
        #pragma unroll
        for (int mi = 0; mi < 2; mi++) {
            const float* p = shA + (wm * 32 + mi * 16 + g) * SA + k0 + t;
            a[mi][0] = __float_as_uint(p[0]);
            a[mi][1] = __float_as_uint(p[8 * SA]);
            a[mi][2] = __float_as_uint(p[4]);
            a[mi][3] = __float_as_uint(p[8 * SA + 4]);
        }
        #pragma unroll
        for (int ni = 0; ni < 8; ni++) {
            const float* q = shB + (k0 + t) * SW + wn * 64 + ni * 8 + g;
            uint32_t b0 = __float_as_uint(q[0]);
            uint32_t b1 = __float_as_uint(q[4 * SW]);
            mma_tile(acc[0][ni], a[0], b0, b1);
            mma_tile(acc[1][ni], a[1], b0, b1);
        }
    }
}

// ---------------------------------------------------------------------------
__global__ void kq_kernel(const float* __restrict__ K, const float* __restrict__ Q) {
    int tid = threadIdx.x;
    int h = tid >> 7, c = tid & 127;
    float s = 0.f;
    #pragma unroll
    for (int d = 0; d < HDIM; d++)
        s += K[h * (IN_DIM * HDIM) + c * HDIM + d] * Q[h * HDIM + d];
    g_kq[h * IN_DIM + c] = s;
}

// alpha[n,h] = x[n].kq[h]; CTA-reduced atomicMax into g_amax.
__global__ void alpha_kernel(const float* __restrict__ x, int nrows) {
    __shared__ float kq_s[512];
    __shared__ float red[32];
    int tid = threadIdx.x;
    kq_s[tid] = g_kq[tid];
    kq_s[tid + 256] = g_kq[tid + 256];
    __syncthreads();
    int wid = tid >> 5, lane = tid & 31;
    int row = blockIdx.x * 8 + wid;
    bool valid = row < nrows;
    float s[4];
    if (valid) {
        float4 xr = *(const float4*)&x[(size_t)row * 128 + lane * 4];
        #pragma unroll
        for (int h = 0; h < 4; h++) {
            float4 k4 = *(const float4*)&kq_s[h * 128 + lane * 4];
            s[h] = warp_sum(xr.x * k4.x + xr.y * k4.y + xr.z * k4.z + xr.w * k4.w);
        }
        if (lane == 0)
            *(float4*)&g_alpha[(size_t)row * 4] = make_float4(s[0], s[1], s[2], s[3]);
    } else {
        s[0] = s[1] = s[2] = s[3] = -1e30f;
    }
    if (lane < 4) red[wid * 4 + lane] = s[lane];
    __syncthreads();
    if (tid < 32) {
        float v = red[tid];                 // [w][h], h = tid&3
        #pragma unroll
        for (int off = 16; off >= 4; off >>= 1)
            v = fmaxf(v, __shfl_xor_sync(0xffffffffu, v, off));
        if (tid < 4 && v > -1e29f) atomicMax(&g_amax[tid], ord_enc(v));
    }
}

// p[n,h] = exp(alpha[n,h] - gmax[h]) in place
__global__ void p_kernel(int nrows) {
    int i = blockIdx.x * blockDim.x + threadIdx.x;
    if (i >= nrows) return;
    float gm0 = ord_dec(g_amax[0]), gm1 = ord_dec(g_amax[1]);
    float gm2 = ord_dec(g_amax[2]), gm3 = ord_dec(g_amax[3]);
    float4 a = *(float4*)&g_alpha[(size_t)i * 4];
    *(float4*)&g_alpha[(size_t)i * 4] =
        make_float4(__expf(a.x - gm0), __expf(a.y - gm1),
                    __expf(a.z - gm2), __expf(a.w - gm3));
}

// ---------------------------------------------------------------------------
__global__ void __launch_bounds__(256, 1)
gemm_xv(const float* __restrict__ x, const float* __restrict__ V, int nrows) {
    extern __shared__ float sm[];
    float* ws = sm;              // B: [c][d*4+h], stride SW
    float* xs = sm + 128 * SW;   // A: [r][c], stride SA (also C staging)
    int tid = threadIdx.x;
    int row0 = blockIdx.x * 128;
    int lane = tid & 31, wid = tid >> 5;
    int wm = wid & 3, wn = wid >> 2;

    for (int idx = tid; idx < 16384; idx += 256) {   // V linear: h,c,d
        int h = idx >> 12, c = (idx >> 5) & 127, d = idx & 31;
        ws[c * SW + d * 4 + h] = to_tf32(V[idx]);
    }
    for (int idx = tid; idx < 4096; idx += 256) {
        int r = idx >> 5, q = idx & 31;
        int row = row0 + r;
        float4 v = (row < nrows) ? *(const float4*)&x[(size_t)row * 128 + q * 4]
                                 : make_float4(0.f, 0.f, 0.f, 0.f);
        xs[r * SA + q * 4 + 0] = to_tf32(v.x);
        xs[r * SA + q * 4 + 1] = to_tf32(v.y);
        xs[r * SA + q * 4 + 2] = to_tf32(v.z);
        xs[r * SA + q * 4 + 3] = to_tf32(v.w);
    }
    __syncthreads();

    float acc[2][8][4];
    #pragma unroll
    for (int i = 0; i < 2; i++)
        #pragma unroll
        for (int j = 0; j < 8; j++)
            #pragma unroll
            for (int k = 0; k < 4; k++) acc[i][j][k] = 0.f;
    gemm_core(xs, ws, acc, wm, wn, lane);
    __syncthreads();

    int g = lane >> 2, t = lane & 3;
    #pragma unroll
    for (int mi = 0; mi < 2; mi++)
        #pragma unroll
        for (int ni = 0; ni < 8; ni++) {
            int r = wm * 32 + mi * 16 + g;
            int c = wn * 64 + ni * 8 + 2 * t;
            *(float2*)&xs[r * SA + c] = make_float2(acc[mi][ni][0], acc[mi][ni][1]);
            *(float2*)&xs[(r + 8) * SA + c] = make_float2(acc[mi][ni][2], acc[mi][ni][3]);
        }
    __syncthreads();

    for (int idx = tid; idx < 4096; idx += 256) {
        int r = idx >> 5, q = idx & 31;
        int row = row0 + r;
        if (row < nrows)
            *(float4*)&g_xv[(size_t)row * 128 + q * 4] = *(float4*)&xs[r * SA + q * 4];
    }
}

// ---------------------------------------------------------------------------
__global__ void hist_kernel(const int* __restrict__ tgt, int E) {
    if (blockIdx.x == 0 && threadIdx.x < 64) g_scst[threadIdx.x] = 0;
    int stride = gridDim.x * blockDim.x;
    int gid = blockIdx.x * blockDim.x + threadIdx.x;
    int n4 = E >> 2;
    const int4* t4 = (const int4*)tgt;
    for (int i = gid; i < n4; i += stride) {
        int4 t = t4[i];
        atomicAdd(&g_cnt[t.x], 1);
        atomicAdd(&g_cnt[t.y], 1);
        atomicAdd(&g_cnt[t.z], 1);
        atomicAdd(&g_cnt[t.w], 1);
    }
    for (int e = n4 * 4 + gid; e < E; e += stride) atomicAdd(&g_cnt[tgt[e]], 1);
}

// single-launch exclusive scan, decoupled lookback (grid <= 50 blocks)
__global__ void scan_kernel(int n, int* __restrict__ off) {
    __shared__ int wsum[32];
    __shared__ int s_excl;
    int tid = threadIdx.x, lane = tid & 31, wid = tid >> 5;
    int bid = blockIdx.x;
    int i = bid * 1024 + tid;
    int v = (i < n) ? g_cnt[i] : 0;
    int x = v;
    #pragma unroll
    for (int o = 1; o < 32; o <<= 1) {
        int t = __shfl_up_sync(0xffffffffu, x, o);
        if (lane >= o) x += t;
    }
    if (lane == 31) wsum[wid] = x;
    __syncthreads();
    if (wid == 0) {
        int s = wsum[lane];
        #pragma unroll
        for (int o = 1; o < 32; o <<= 1) {
            int t = __shfl_up_sync(0xffffffffu, s, o);
            if (lane >= o) s += t;
        }
        wsum[lane] = s;
    }
    __syncthreads();
    int base = (wid > 0) ? wsum[wid - 1] : 0;
    int incl = base + x;
    int local_total = wsum[31];

    if (tid == 0) {
        int run = 0;
        if (bid > 0) {
            atomicExch(&g_scst[bid], (local_total << 2) | 1);
            int j = bid - 1;
            while (j >= 0) {
                int st = atomicAdd(&g_scst[j], 0);
                int tag = st & 3;
                if (tag == 2) { run += st >> 2; break; }
                if (tag == 1) { run += st >> 2; j--; }
            }
        }
        atomicExch(&g_scst[bid], ((run + local_total) << 2) | 2);
        s_excl = run;
    }
    __syncthreads();
    int e = s_excl + incl - v;
    if (i < n) { off[i] = e; g_cur[i] = e; }
    if (bid == gridDim.x - 1 && tid == 1023) off[n] = s_excl + local_total;
}

__global__ void scatter_kernel(const int* __restrict__ tgt,
                               const int* __restrict__ src,
                               int* __restrict__ esrc, int E) {
    int stride = gridDim.x * blockDim.x;
    int gid = blockIdx.x * blockDim.x + threadIdx.x;
    int n4 = E >> 2;
    const int4* t4 = (const int4*)tgt;
    const int4* s4 = (const int4*)src;
    for (int i = gid; i < n4; i += stride) {
        int4 t = t4[i]; int4 s = s4[i];
        int p;
        p = atomicAdd(&g_cur[t.x], 1); esrc[p] = s.x;
        p = atomicAdd(&g_cur[t.y], 1); esrc[p] = s.y;
        p = atomicAdd(&g_cur[t.z], 1); esrc[p] = s.z;
        p = atomicAdd(&g_cur[t.w], 1); esrc[p] = s.w;
    }
    for (int e = n4 * 4 + gid; e < E; e += stride) {
        int p = atomicAdd(&g_cur[tgt[e]], 1); esrc[p] = src[e];
    }
}

// ---------------------------------------------------------------------------
// Single pass: acc += p_j * v_j, s += p_j; out = acc/s + bias. No per-edge exp.
__global__ void __launch_bounds__(256)
segagg_kernel(const int* __restrict__ esrc, const int* __restrict__ off,
              const float* __restrict__ qbias, int n_tgt) {
    __shared__ int    sh_sn[256];
    __shared__ float4 sh_p[256];
    int wid = threadIdx.x >> 5, lane = threadIdx.x & 31;
    int gw = blockIdx.x * 8 + wid;
    if (gw >= n_tgt) return;
    int start = off[gw], end = off[gw + 1];
    float* outrow = &g_S1[(size_t)gw * 128];

    if (end == start) {
        #pragma unroll
        for (int k = 0; k < 4; k++) outrow[k * 32 + lane] = qbias[k * 32 + lane];
        return;
    }

    int sbase = wid * 32;
    float acc[4] = {0.f, 0.f, 0.f, 0.f};
    float4 sacc = make_float4(0.f, 0.f, 0.f, 0.f);
    for (int i0 = start; i0 < end; i0 += 32) {
        int cnt = end - i0; if (cnt > 32) cnt = 32;
        if (lane < cnt) {
            int sn = __ldg(&esrc[i0 + lane]);
            float4 p4 = *(const float4*)&g_alpha[(size_t)sn * 4];
            sh_sn[sbase + lane] = sn;
            sh_p[sbase + lane] = p4;
            sacc.x += p4.x; sacc.y += p4.y; sacc.z += p4.z; sacc.w += p4.w;
        }
        __syncwarp();
        #pragma unroll 4
        for (int j = 0; j < cnt; j++) {
            int sn = sh_sn[sbase + j];
            float4 pv = sh_p[sbase + j];
            float4 v = *(const float4*)&g_xv[(size_t)sn * 128 + lane * 4];
            acc[0] += pv.x * v.x; acc[1] += pv.y * v.y;
            acc[2] += pv.z * v.z; acc[3] += pv.w * v.w;
        }
        __syncwarp();
    }
    float inv0 = 1.0f / warp_sum(sacc.x);
    float inv1 = 1.0f / warp_sum(sacc.y);
    float inv2 = 1.0f / warp_sum(sacc.z);
    float inv3 = 1.0f / warp_sum(sacc.w);
    outrow[lane]      = acc[0] * inv0 + qbias[lane];
    outrow[32 + lane] = acc[1] * inv1 + qbias[32 + lane];
    outrow[64 + lane] = acc[2] * inv2 + qbias[64 + lane];
    outrow[96 + lane] = acc[3] * inv3 + qbias[96 + lane];
}

// ---------------------------------------------------------------------------
__global__ void __launch_bounds__(256, 1)
mlp_kernel(const float* __restrict__ g0, const float* __restrict__ b0,
           const float* __restrict__ W1, const float* __restrict__ W2,
           const float* __restrict__ g1, const float* __restrict__ b1,
           float* __restrict__ out, int nrows) {
    extern __shared__ float sm[];
    float* sh_h = sm;                       // [128][SA]
    float* sh_t = sm + 128 * SA;            // [128][SA]
    float* sh_w = sm + 256 * SA;            // [128][SW]
    int tid = threadIdx.x;
    int row0 = blockIdx.x * 128;
    int wid = tid >> 5, lane = tid & 31;
    int wm = wid & 3, wn = wid >> 2;
    int g = lane >> 2, t = lane & 3;

    for (int idx = tid; idx < 4096; idx += 256) {
        int r = idx >> 5, q = idx & 31;
        int row = row0 + r;
        float4 v = (row < nrows) ? *(const float4*)&g_S1[(size_t)row * 128 + q * 4]
                                 : make_float4(0.f, 0.f, 0.f, 0.f);
        *(float4*)&sh_h[r * SA + q * 4] = v;
    }
    for (int idx = tid; idx < 4096; idx += 256) {
        float4 v = *(const float4*)&W1[idx * 4];
        int r = idx >> 5, q = idx & 31;
        sh_w[r * SW + q * 4 + 0] = to_tf32(v.x);
        sh_w[r * SW + q * 4 + 1] = to_tf32(v.y);
        sh_w[r * SW + q * 4 + 2] = to_tf32(v.z);
        sh_w[r * SW + q * 4 + 3] = to_tf32(v.w);
    }
    __syncthreads();

    float4 gA = *(const float4*)&g0[lane * 4];
    float4 bA = *(const float4*)&b0[lane * 4];
    for (int r = wid; r < 128; r += 8) {
        float4 v = *(float4*)&sh_h[r * SA + lane * 4];
        float mean = warp_sum(v.x + v.y + v.z + v.w) * (1.f / 128.f);
        float dx = v.x - mean, dy = v.y - mean, dz = v.z - mean, dw = v.w - mean;
        float var = warp_sum(dx * dx + dy * dy + dz * dz + dw * dw) * (1.f / 128.f);
        float rstd = rsqrtf(var + 1e-5f);
        sh_h[r * SA + lane * 4 + 0] = to_tf32(dx * rstd * gA.x + bA.x);
        sh_h[r * SA + lane * 4 + 1] = to_tf32(dy * rstd * gA.y + bA.y);
        sh_h[r * SA + lane * 4 + 2] = to_tf32(dz * rstd * gA.z + bA.z);
        sh_h[r * SA + lane * 4 + 3] = to_tf32(dw * rstd * gA.w + bA.w);
    }
    __syncthreads();

    float acc[2][8][4];
    #pragma unroll
    for (int i = 0; i < 2; i++)
        #pragma unroll
        for (int j = 0; j < 8; j++)
            #pragma unroll
            for (int k = 0; k < 4; k++) acc[i][j][k] = 0.f;
    gemm_core(sh_h, sh_w, acc, wm, wn, lane);

    #pragma unroll
    for (int mi = 0; mi < 2; mi++)
        #pragma unroll
        for (int ni = 0; ni < 8; ni++) {
            int r = wm * 32 + mi * 16 + g;
            int c = wn * 64 + ni * 8 + 2 * t;
            sh_t[r * SA + c]           = to_tf32(fmaxf(acc[mi][ni][0], 0.f));
            sh_t[r * SA + c + 1]       = to_tf32(fmaxf(acc[mi][ni][1], 0.f));
            sh_t[(r + 8) * SA + c]     = to_tf32(fmaxf(acc[mi][ni][2], 0.f));
            sh_t[(r + 8) * SA + c + 1] = to_tf32(fmaxf(acc[mi][ni][3], 0.f));
        }
    __syncthreads();

    for (int idx = tid; idx < 4096; idx += 256) {
        float4 v = *(const float4*)&W2[idx * 4];
        int r = idx >> 5, q = idx & 31;
        sh_w[r * SW + q * 4 + 0] = to_tf32(v.x);
        sh_w[r * SW + q * 4 + 1] = to_tf32(v.y);
        sh_w[r * SW + q * 4 + 2] = to_tf32(v.z);
        sh_w[r * SW + q * 4 + 3] = to_tf32(v.w);
    }
    __syncthreads();

    #pragma unroll
    for (int i = 0; i < 2; i++)
        #pragma unroll
        for (int j = 0; j < 8; j++)
            #pragma unroll
            for (int k = 0; k < 4; k++) acc[i][j][k] = 0.f;
    gemm_core(sh_t, sh_w, acc, wm, wn, lane);
    __syncthreads();

    #pragma unroll
    for (int mi = 0; mi < 2; mi++)
        #pragma unroll
        for (int ni = 0; ni < 8; ni++) {
            int r = wm * 32 + mi * 16 + g;
            int c = wn * 64 + ni * 8 + 2 * t;
            sh_t[r * SA + c]           = sh_h[r * SA + c] + fmaxf(acc[mi][ni][0], 0.f);
            sh_t[r * SA + c + 1]       = sh_h[r * SA + c + 1] + fmaxf(acc[mi][ni][1], 0.f);
            sh_t[(r + 8) * SA + c]     = sh_h[(r + 8) * SA + c] + fmaxf(acc[mi][ni][2], 0.f);
            sh_t[(r + 8) * SA + c + 1] = sh_h[(r + 8) * SA + c + 1] + fmaxf(acc[mi][ni][3], 0.f);
        }
    __syncthreads();

    float4 gB = *(const float4*)&g1[lane * 4];
    float4 bB = *(const float4*)&b1[lane * 4];
    for (int r = wid; r < 128; r += 8) {
        float4 v = *(float4*)&sh_t[r * SA + lane * 4];
        float mean = warp_sum(v.x + v.y + v.z + v.w) * (1.f / 128.f);
        float dx = v.x - mean, dy = v.y - mean, dz = v.z - mean, dw = v.w - mean;
        float var = warp_sum(dx * dx + dy * dy + dz * dz + dw * dw) * (1.f / 128.f);
        float rstd = rsqrtf(var + 1e-5f);
        int row = row0 + r;
        if (row < nrows) {
            *(float4*)&out[(size_t)row * 128 + lane * 4] =
                make_float4(fmaxf(dx * rstd * gB.x + bB.x, 0.f),
                            fmaxf(dy * rstd * gB.y + bB.y, 0.f),
                            fmaxf(dz * rstd * gB.z + bB.z, 0.f),
                            fmaxf(dw * rstd * gB.w + bB.w, 0.f));
        }
    }
}

// ---------------------------------------------------------------------------
extern "C" void kernel_launch(void* const* d_in, const int* in_sizes, int n_in,
                              void* d_out, int out_size) {
    const int N = in_sizes[0] / IN_DIM;
    const int E = in_sizes[1];
    const int M = out_size / IN_DIM - N;

    const int wi = n_in - 18;
    const float* x0 = (const float*)d_in[0];
    const int* node_idx  = (const int*)d_in[1];
    const int* hedge_idx = (const int*)d_in[2];
    const float* w[18];
    for (int i = 0; i < 18; i++) w[i] = (const float*)d_in[wi + i];

    float* out = (float*)d_out;            // x_0_out [N,128]
    float* x1  = out + (size_t)N * IN_DIM; // x_1     [M,128]

    const int gemmSmem = (128 * SW + 128 * SA) * 4;
    const int mlpSmem  = (256 * SA + 128 * SW) * 4;

    static int s_init = 0;
    static cudaStream_t s2;
    static cudaEvent_t evFork, evA, evB;
    static void *cnt_ptr, *offA_ptr, *offB_ptr, *esrcA_ptr, *esrcB_ptr, *amax_ptr;
    if (!s_init) {
        cudaFuncSetAttribute(gemm_xv,
                             cudaFuncAttributeMaxDynamicSharedMemorySize, gemmSmem);
        cudaFuncSetAttribute(mlp_kernel,
                             cudaFuncAttributeMaxDynamicSharedMemorySize, mlpSmem);
        cudaStreamCreateWithFlags(&s2, cudaStreamNonBlocking);
        cudaEventCreateWithFlags(&evFork, cudaEventDisableTiming);
        cudaEventCreateWithFlags(&evA, cudaEventDisableTiming);
        cudaEventCreateWithFlags(&evB, cudaEventDisableTiming);
        cudaGetSymbolAddress(&cnt_ptr, g_cnt);
        cudaGetSymbolAddress(&offA_ptr, g_offA);
        cudaGetSymbolAddress(&offB_ptr, g_offB);
        cudaGetSymbolAddress(&esrcA_ptr, g_esrcA);
        cudaGetSymbolAddress(&esrcB_ptr, g_esrcB);
        cudaGetSymbolAddress(&amax_ptr, g_amax);
        s_init = 1;
    }
    int* offA = (int*)offA_ptr;
    int* offB = (int*)offB_ptr;
    int* esrcA = (int*)esrcA_ptr;
    int* esrcB = (int*)esrcB_ptr;

    const int nbM = (M + 1023) / 1024, nbN = (N + 1023) / 1024;

    cudaEventRecord(evFork, 0);
    cudaStreamWaitEvent(s2, evFork, 0);

    // s2: CSR A (targets = hyperedges)
    cudaMemsetAsync(cnt_ptr, 0, sizeof(int) * (M + 1), s2);
    hist_kernel<<<512, 256, 0, s2>>>(hedge_idx, E);
    scan_kernel<<<nbM, 1024, 0, s2>>>(M, offA);
    scatter_kernel<<<512, 256, 0, s2>>>(hedge_idx, node_idx, esrcA, E);
    cudaEventRecord(evA, s2);
    // s2: CSR B (targets = nodes)
    cudaMemsetAsync(cnt_ptr, 0, sizeof(int) * (N + 1), s2);
    hist_kernel<<<512, 256, 0, s2>>>(node_idx, E);
    scan_kernel<<<nbN, 1024, 0, s2>>>(N, offB);
    scatter_kernel<<<512, 256, 0, s2>>>(node_idx, hedge_idx, esrcB, E);
    cudaEventRecord(evB, s2);

    // stream 0: phase 1 (v2e)
    cudaMemsetAsync(amax_ptr, 0, 16, 0);
    kq_kernel<<<1, 512>>>(w[0], w[1]);
    gemm_xv<<<(N + 127) / 128, 256, gemmSmem>>>(x0, w[2], N);
    alpha_kernel<<<(N + 7) / 8, 256>>>(x0, N);
    p_kernel<<<(N + 255) / 256, 256>>>(N);
    cudaStreamWaitEvent(0, evA, 0);
    segagg_kernel<<<(M + 7) / 8, 256>>>(esrcA, offA, w[1], M);
    mlp_kernel<<<(M + 127) / 128, 256, mlpSmem>>>(w[3], w[4], w[5], w[6], w[7],
                                                  w[8], x1, M);
    // phase 2 (e2v)
    cudaMemsetAsync(amax_ptr, 0, 16, 0);
    kq_kernel<<<1, 512>>>(w[9], w[10]);
    gemm_xv<<<(M + 127) / 128, 256, gemmSmem>>>(x1, w[11], M);
    alpha_kernel<<<(M + 7) / 8, 256>>>(x1, M);
    p_kernel<<<(M + 255) / 256, 256>>>(M);
    cudaStreamWaitEvent(0, evB, 0);
    segagg_kernel<<<(N + 7) / 8, 256>>>(esrcB, offB, w[10], N);
    mlp_kernel<<<(N + 127) / 128, 256, mlpSmem>>>(w[12], w[13], w[14], w[15],
                                                  w[16], w[17], out, N);
}

// round 9
// speedup vs baseline: 1.4325x; 1.3282x over previous
#include <cuda_runtime.h>
#include <math.h>
#include <stdint.h>

#define IN_DIM 128
#define NHEAD 4
#define HDIM 32
#define MAX_ROWS 51200
#define MAX_E 1050000
#define SA 132   // smem stride activation tiles
#define SW 136   // smem stride weight tiles

__device__ __align__(16) float g_p[MAX_ROWS * NHEAD];    // [n][h] p = exp(alpha)
__device__ __align__(16) float g_xv[MAX_ROWS * IN_DIM];  // [n][d*4+h]
__device__ __align__(16) float g_S1[MAX_ROWS * IN_DIM];  // pre-MLP features
__device__ int g_esrcA[MAX_E];
__device__ int g_esrcB[MAX_E];
__device__ int g_offA[MAX_ROWS + 1];
__device__ int g_offB[MAX_ROWS + 1];
__device__ int g_cnt[MAX_ROWS + 1];
__device__ int g_cur[MAX_ROWS + 1];
__device__ int g_scst[64];                 // lookback states

__device__ __forceinline__ float warp_sum(float v) {
    #pragma unroll
    for (int off = 16; off; off >>= 1) v += __shfl_xor_sync(0xffffffffu, v, off);
    return v;
}

__device__ __forceinline__ float to_tf32(float x) {
    uint32_t u;
    asm("cvt.rna.tf32.f32 %0, %1;" : "=r"(u) : "f"(x));
    return __uint_as_float(u);
}

__device__ __forceinline__ void mma_tile(float c[4], const uint32_t a[4],
                                         uint32_t b0, uint32_t b1) {
    asm volatile(
        "mma.sync.aligned.m16n8k8.row.col.f32.tf32.tf32.f32 "
        "{%0,%1,%2,%3}, {%4,%5,%6,%7}, {%8,%9}, {%0,%1,%2,%3};"
        : "+f"(c[0]), "+f"(c[1]), "+f"(c[2]), "+f"(c[3])
        : "r"(a[0]), "r"(a[1]), "r"(a[2]), "r"(a[3]), "r"(b0), "r"(b1));
}

// 128x128x128: 8 warps, wm = wid&3 (32 rows), wn = wid>>2 (64 cols)
__device__ __forceinline__ void gemm_core(const float* __restrict__ shA,
                                          const float* __restrict__ shB,
                                          float acc[2][8][4],
                                          int wm, int wn, int lane) {
    int g = lane >> 2, t = lane & 3;
    #pragma unroll 2
    for (int k0 = 0; k0 < 128; k0 += 8) {
        uint32_t a[2][4];
        #pragma unroll
        for (int mi = 0; mi < 2; mi++) {
            const float* p = shA + (wm * 32 + mi * 16 + g) * SA + k0 + t;
            a[mi][0] = __float_as_uint(p[0]);
            a[mi][1] = __float_as_uint(p[8 * SA]);
            a[mi][2] = __float_as_uint(p[4]);
            a[mi][3] = __float_as_uint(p[8 * SA + 4]);
        }
        #pragma unroll
        for (int ni = 0; ni < 8; ni++) {
            const float* q = shB + (k0 + t) * SW + wn * 64 + ni * 8 + g;
            uint32_t b0 = __float_as_uint(q[0]);
            uint32_t b1 = __float_as_uint(q[4 * SW]);
            mma_tile(acc[0][ni], a[0], b0, b1);
            mma_tile(acc[1][ni], a[1], b0, b1);
        }
    }
}

// 64x128x128: 8 warps, wm = wid&1 (32 rows), wn = wid>>1 (32 cols)
__device__ __forceinline__ void gemm_core64(const float* __restrict__ shA,
                                            const float* __restrict__ shB,
                                            float acc[2][4][4],
                                            int wm, int wn, int lane) {
    int g = lane >> 2, t = lane & 3;
    #pragma unroll 2
    for (int k0 = 0; k0 < 128; k0 += 8) {
        uint32_t a[2][4];
        #pragma unroll
        for (int mi = 0; mi < 2; mi++) {
            const float* p = shA + (wm * 32 + mi * 16 + g) * SA + k0 + t;
            a[mi][0] = __float_as_uint(p[0]);
            a[mi][1] = __float_as_uint(p[8 * SA]);
            a[mi][2] = __float_as_uint(p[4]);
            a[mi][3] = __float_as_uint(p[8 * SA + 4]);
        }
        #pragma unroll
        for (int ni = 0; ni < 4; ni++) {
            const float* q = shB + (k0 + t) * SW + wn * 32 + ni * 8 + g;
            uint32_t b0 = __float_as_uint(q[0]);
            uint32_t b1 = __float_as_uint(q[4 * SW]);
            mma_tile(acc[0][ni], a[0], b0, b1);
            mma_tile(acc[1][ni], a[1], b0, b1);
        }
    }
}

// ---------------------------------------------------------------------------
// Persistent: V + kq resident; loop over 128-row tiles.
// Per tile: xv = x@V_cat (tf32 MMA), p = exp(x . kq) from the smem x tile.
__global__ void __launch_bounds__(256, 1)
gemm_xv(const float* __restrict__ x, const float* __restrict__ V,
        const float* __restrict__ K, const float* __restrict__ Q,
        int nrows, int ntiles) {
    extern __shared__ float sm[];
    float* ws = sm;                         // [c][d*4+h], stride SW
    float* xs = sm + 128 * SW;              // [r][c], stride SA (also C staging)
    float* kq_s = sm + 128 * SW + 128 * SA; // [h*132 + c]
    int tid = threadIdx.x;
    int lane = tid & 31, wid = tid >> 5;
    int wm = wid & 3, wn = wid >> 2;
    int g = lane >> 2, t = lane & 3;

    // one-time: kq + V (permuted, tf32)
    #pragma unroll
    for (int idx = tid; idx < 512; idx += 256) {
        int h = idx >> 7, c = idx & 127;
        float s = 0.f;
        #pragma unroll
        for (int d = 0; d < HDIM; d++)
            s += K[h * (IN_DIM * HDIM) + c * HDIM + d] * Q[h * HDIM + d];
        kq_s[h * 132 + c] = s;
    }
    for (int idx = tid; idx < 16384; idx += 256) {   // V linear: h,c,d
        int h = idx >> 12, c = (idx >> 5) & 127, d = idx & 31;
        ws[c * SW + d * 4 + h] = to_tf32(V[idx]);
    }
    __syncthreads();

    for (int tile = blockIdx.x; tile < ntiles; tile += gridDim.x) {
        int row0 = tile * 128;
        for (int idx = tid; idx < 4096; idx += 256) {
            int r = idx >> 5, q = idx & 31;
            int row = row0 + r;
            float4 v = (row < nrows) ? *(const float4*)&x[(size_t)row * 128 + q * 4]
                                     : make_float4(0.f, 0.f, 0.f, 0.f);
            xs[r * SA + q * 4 + 0] = to_tf32(v.x);
            xs[r * SA + q * 4 + 1] = to_tf32(v.y);
            xs[r * SA + q * 4 + 2] = to_tf32(v.z);
            xs[r * SA + q * 4 + 3] = to_tf32(v.w);
        }
        __syncthreads();

        float acc[2][8][4];
        #pragma unroll
        for (int i = 0; i < 2; i++)
            #pragma unroll
            for (int j = 0; j < 8; j++)
                #pragma unroll
                for (int k = 0; k < 4; k++) acc[i][j][k] = 0.f;
        gemm_core(xs, ws, acc, wm, wn, lane);

        // p = exp(x . kq): 512 tasks, 2 per thread (xs still intact)
        #pragma unroll
        for (int t2 = 0; t2 < 2; t2++) {
            int task = tid + 256 * t2;
            int r = task >> 2, h = task & 3;
            const float* xr = &xs[r * SA];
            const float* kr = &kq_s[h * 132];
            float s = 0.f;
            #pragma unroll 4
            for (int c = 0; c < 128; c++) s += xr[c] * kr[c];
            int row = row0 + r;
            if (row < nrows) g_p[(size_t)row * 4 + h] = __expf(s);
        }
        __syncthreads();

        #pragma unroll
        for (int mi = 0; mi < 2; mi++)
            #pragma unroll
            for (int ni = 0; ni < 8; ni++) {
                int r = wm * 32 + mi * 16 + g;
                int c = wn * 64 + ni * 8 + 2 * t;
                *(float2*)&xs[r * SA + c] = make_float2(acc[mi][ni][0], acc[mi][ni][1]);
                *(float2*)&xs[(r + 8) * SA + c] = make_float2(acc[mi][ni][2], acc[mi][ni][3]);
            }
        __syncthreads();

        for (int idx = tid; idx < 4096; idx += 256) {
            int r = idx >> 5, q = idx & 31;
            int row = row0 + r;
            if (row < nrows)
                *(float4*)&g_xv[(size_t)row * 128 + q * 4] = *(float4*)&xs[r * SA + q * 4];
        }
        __syncthreads();
    }
}

// ---------------------------------------------------------------------------
__global__ void hist_kernel(const int* __restrict__ tgt, int E) {
    if (blockIdx.x == 0 && threadIdx.x < 64) g_scst[threadIdx.x] = 0;
    int stride = gridDim.x * blockDim.x;
    int gid = blockIdx.x * blockDim.x + threadIdx.x;
    int n4 = E >> 2;
    const int4* t4 = (const int4*)tgt;
    for (int i = gid; i < n4; i += stride) {
        int4 t = t4[i];
        atomicAdd(&g_cnt[t.x], 1);
        atomicAdd(&g_cnt[t.y], 1);
        atomicAdd(&g_cnt[t.z], 1);
        atomicAdd(&g_cnt[t.w], 1);
    }
    for (int e = n4 * 4 + gid; e < E; e += stride) atomicAdd(&g_cnt[tgt[e]], 1);
}

// single-launch exclusive scan, decoupled lookback (grid <= 50 blocks)
__global__ void scan_kernel(int n, int* __restrict__ off) {
    __shared__ int wsum[32];
    __shared__ int s_excl;
    int tid = threadIdx.x, lane = tid & 31, wid = tid >> 5;
    int bid = blockIdx.x;
    int i = bid * 1024 + tid;
    int v = (i < n) ? g_cnt[i] : 0;
    int x = v;
    #pragma unroll
    for (int o = 1; o < 32; o <<= 1) {
        int t = __shfl_up_sync(0xffffffffu, x, o);
        if (lane >= o) x += t;
    }
    if (lane == 31) wsum[wid] = x;
    __syncthreads();
    if (wid == 0) {
        int s = wsum[lane];
        #pragma unroll
        for (int o = 1; o < 32; o <<= 1) {
            int t = __shfl_up_sync(0xffffffffu, s, o);
            if (lane >= o) s += t;
        }
        wsum[lane] = s;
    }
    __syncthreads();
    int base = (wid > 0) ? wsum[wid - 1] : 0;
    int incl = base + x;
    int local_total = wsum[31];

    if (tid == 0) {
        int run = 0;
        if (bid > 0) {
            atomicExch(&g_scst[bid], (local_total << 2) | 1);
            int j = bid - 1;
            while (j >= 0) {
                int st = atomicAdd(&g_scst[j], 0);
                int tag = st & 3;
                if (tag == 2) { run += st >> 2; break; }
                if (tag == 1) { run += st >> 2; j--; }
            }
        }
        atomicExch(&g_scst[bid], ((run + local_total) << 2) | 2);
        s_excl = run;
    }
    __syncthreads();
    int e = s_excl + incl - v;
    if (i < n) { off[i] = e; g_cur[i] = e; }
    if (bid == gridDim.x - 1 && tid == 1023) off[n] = s_excl + local_total;
}

__global__ void scatter_kernel(const int* __restrict__ tgt,
                               const int* __restrict__ src,
                               int* __restrict__ esrc, int E) {
    int stride = gridDim.x * blockDim.x;
    int gid = blockIdx.x * blockDim.x + threadIdx.x;
    int n4 = E >> 2;
    const int4* t4 = (const int4*)tgt;
    const int4* s4 = (const int4*)src;
    for (int i = gid; i < n4; i += stride) {
        int4 t = t4[i]; int4 s = s4[i];
        int p;
        p = atomicAdd(&g_cur[t.x], 1); esrc[p] = s.x;
        p = atomicAdd(&g_cur[t.y], 1); esrc[p] = s.y;
        p = atomicAdd(&g_cur[t.z], 1); esrc[p] = s.z;
        p = atomicAdd(&g_cur[t.w], 1); esrc[p] = s.w;
    }
    for (int e = n4 * 4 + gid; e < E; e += stride) {
        int p = atomicAdd(&g_cur[tgt[e]], 1); esrc[p] = src[e];
    }
}

// ---------------------------------------------------------------------------
// Single pass: acc += p_j * v_j, s += p_j; out = acc/s + bias.
__global__ void __launch_bounds__(256)
segagg_kernel(const int* __restrict__ esrc, const int* __restrict__ off,
              const float* __restrict__ qbias, int n_tgt) {
    __shared__ int    sh_sn[256];
    __shared__ float4 sh_p[256];
    int wid = threadIdx.x >> 5, lane = threadIdx.x & 31;
    int gw = blockIdx.x * 8 + wid;
    if (gw >= n_tgt) return;
    int start = off[gw], end = off[gw + 1];
    float* outrow = &g_S1[(size_t)gw * 128];

    if (end == start) {
        #pragma unroll
        for (int k = 0; k < 4; k++) outrow[k * 32 + lane] = qbias[k * 32 + lane];
        return;
    }

    int sbase = wid * 32;
    float acc[4] = {0.f, 0.f, 0.f, 0.f};
    float4 sacc = make_float4(0.f, 0.f, 0.f, 0.f);
    for (int i0 = start; i0 < end; i0 += 32) {
        int cnt = end - i0; if (cnt > 32) cnt = 32;
        if (lane < cnt) {
            int sn = __ldg(&esrc[i0 + lane]);
            float4 p4 = *(const float4*)&g_p[(size_t)sn * 4];
            sh_sn[sbase + lane] = sn;
            sh_p[sbase + lane] = p4;
            sacc.x += p4.x; sacc.y += p4.y; sacc.z += p4.z; sacc.w += p4.w;
        }
        __syncwarp();
        #pragma unroll 4
        for (int j = 0; j < cnt; j++) {
            int sn = sh_sn[sbase + j];
            float4 pv = sh_p[sbase + j];
            float4 v = *(const float4*)&g_xv[(size_t)sn * 128 + lane * 4];
            acc[0] += pv.x * v.x; acc[1] += pv.y * v.y;
            acc[2] += pv.z * v.z; acc[3] += pv.w * v.w;
        }
        __syncwarp();
    }
    float inv0 = 1.0f / warp_sum(sacc.x);
    float inv1 = 1.0f / warp_sum(sacc.y);
    float inv2 = 1.0f / warp_sum(sacc.z);
    float inv3 = 1.0f / warp_sum(sacc.w);
    outrow[lane]      = acc[0] * inv0 + qbias[lane];
    outrow[32 + lane] = acc[1] * inv1 + qbias[32 + lane];
    outrow[64 + lane] = acc[2] * inv2 + qbias[64 + lane];
    outrow[96 + lane] = acc[3] * inv3 + qbias[96 + lane];
}

// ---------------------------------------------------------------------------
// Persistent MLP: W1+W2 resident in smem, loop over 64-row tiles.
// LN0 -> relu(h@W1) -> relu(t@W2) -> residual -> LN1 -> relu.
__global__ void __launch_bounds__(256, 1)
mlp_kernel(const float* __restrict__ g0, const float* __restrict__ b0,
           const float* __restrict__ W1, const float* __restrict__ W2,
           const float* __restrict__ g1, const float* __restrict__ b1,
           float* __restrict__ out, int nrows, int ntiles) {
    extern __shared__ float sm[];
    float* sh_w1 = sm;                      // [128][SW]
    float* sh_w2 = sm + 128 * SW;           // [128][SW]
    float* sh_h  = sm + 256 * SW;           // [64][SA]
    float* sh_t  = sm + 256 * SW + 64 * SA; // [64][SA]
    int tid = threadIdx.x;
    int wid = tid >> 5, lane = tid & 31;
    int wm = wid & 1, wn = wid >> 1;
    int g = lane >> 2, t = lane & 3;

    for (int idx = tid; idx < 4096; idx += 256) {
        float4 v1 = *(const float4*)&W1[idx * 4];
        float4 v2 = *(const float4*)&W2[idx * 4];
        int r = idx >> 5, q = idx & 31;
        sh_w1[r * SW + q * 4 + 0] = to_tf32(v1.x);
        sh_w1[r * SW + q * 4 + 1] = to_tf32(v1.y);
        sh_w1[r * SW + q * 4 + 2] = to_tf32(v1.z);
        sh_w1[r * SW + q * 4 + 3] = to_tf32(v1.w);
        sh_w2[r * SW + q * 4 + 0] = to_tf32(v2.x);
        sh_w2[r * SW + q * 4 + 1] = to_tf32(v2.y);
        sh_w2[r * SW + q * 4 + 2] = to_tf32(v2.z);
        sh_w2[r * SW + q * 4 + 3] = to_tf32(v2.w);
    }
    float4 gA = *(const float4*)&g0[lane * 4];
    float4 bA = *(const float4*)&b0[lane * 4];
    float4 gB = *(const float4*)&g1[lane * 4];
    float4 bB = *(const float4*)&b1[lane * 4];
    __syncthreads();

    for (int tile = blockIdx.x; tile < ntiles; tile += gridDim.x) {
        int row0 = tile * 64;
        for (int idx = tid; idx < 2048; idx += 256) {
            int r = idx >> 5, q = idx & 31;
            int row = row0 + r;
            float4 v = (row < nrows) ? *(const float4*)&g_S1[(size_t)row * 128 + q * 4]
                                     : make_float4(0.f, 0.f, 0.f, 0.f);
            *(float4*)&sh_h[r * SA + q * 4] = v;
        }
        __syncthreads();

        // LN0 in place (tf32 out)
        for (int r = wid; r < 64; r += 8) {
            float4 v = *(float4*)&sh_h[r * SA + lane * 4];
            float mean = warp_sum(v.x + v.y + v.z + v.w) * (1.f / 128.f);
            float dx = v.x - mean, dy = v.y - mean, dz = v.z - mean, dw = v.w - mean;
            float var = warp_sum(dx * dx + dy * dy + dz * dz + dw * dw) * (1.f / 128.f);
            float rstd = rsqrtf(var + 1e-5f);
            sh_h[r * SA + lane * 4 + 0] = to_tf32(dx * rstd * gA.x + bA.x);
            sh_h[r * SA + lane * 4 + 1] = to_tf32(dy * rstd * gA.y + bA.y);
            sh_h[r * SA + lane * 4 + 2] = to_tf32(dz * rstd * gA.z + bA.z);
            sh_h[r * SA + lane * 4 + 3] = to_tf32(dw * rstd * gA.w + bA.w);
        }
        __syncthreads();

        float acc[2][4][4];
        #pragma unroll
        for (int i = 0; i < 2; i++)
            #pragma unroll
            for (int j = 0; j < 4; j++)
                #pragma unroll
                for (int k = 0; k < 4; k++) acc[i][j][k] = 0.f;
        gemm_core64(sh_h, sh_w1, acc, wm, wn, lane);

        // residual h at this thread's C positions
        float hres[2][4][4];
        #pragma unroll
        for (int mi = 0; mi < 2; mi++)
            #pragma unroll
            for (int ni = 0; ni < 4; ni++) {
                int r = wm * 32 + mi * 16 + g;
                int c = wn * 32 + ni * 8 + 2 * t;
                hres[mi][ni][0] = sh_h[r * SA + c];
                hres[mi][ni][1] = sh_h[r * SA + c + 1];
                hres[mi][ni][2] = sh_h[(r + 8) * SA + c];
                hres[mi][ni][3] = sh_h[(r + 8) * SA + c + 1];
            }
        // t = relu(acc) tf32 -> sh_t
        #pragma unroll
        for (int mi = 0; mi < 2; mi++)
            #pragma unroll
            for (int ni = 0; ni < 4; ni++) {
                int r = wm * 32 + mi * 16 + g;
                int c = wn * 32 + ni * 8 + 2 * t;
                sh_t[r * SA + c]           = to_tf32(fmaxf(acc[mi][ni][0], 0.f));
                sh_t[r * SA + c + 1]       = to_tf32(fmaxf(acc[mi][ni][1], 0.f));
                sh_t[(r + 8) * SA + c]     = to_tf32(fmaxf(acc[mi][ni][2], 0.f));
                sh_t[(r + 8) * SA + c + 1] = to_tf32(fmaxf(acc[mi][ni][3], 0.f));
            }
        __syncthreads();

        #pragma unroll
        for (int i = 0; i < 2; i++)
            #pragma unroll
            for (int j = 0; j < 4; j++)
                #pragma unroll
                for (int k = 0; k < 4; k++) acc[i][j][k] = 0.f;
        gemm_core64(sh_t, sh_w2, acc, wm, wn, lane);
        __syncthreads();   // all sh_t reads done

        #pragma unroll
        for (int mi = 0; mi < 2; mi++)
            #pragma unroll
            for (int ni = 0; ni < 4; ni++) {
                int r = wm * 32 + mi * 16 + g;
                int c = wn * 32 + ni * 8 + 2 * t;
                sh_t[r * SA + c]           = hres[mi][ni][0] + fmaxf(acc[mi][ni][0], 0.f);
                sh_t[r * SA + c + 1]       = hres[mi][ni][1] + fmaxf(acc[mi][ni][1], 0.f);
                sh_t[(r + 8) * SA + c]     = hres[mi][ni][2] + fmaxf(acc[mi][ni][2], 0.f);
                sh_t[(r + 8) * SA + c + 1] = hres[mi][ni][3] + fmaxf(acc[mi][ni][3], 0.f);
            }
        __syncthreads();

        for (int r = wid; r < 64; r += 8) {
            float4 v = *(float4*)&sh_t[r * SA + lane * 4];
            float mean = warp_sum(v.x + v.y + v.z + v.w) * (1.f / 128.f);
            float dx = v.x - mean, dy = v.y - mean, dz = v.z - mean, dw = v.w - mean;
            float var = warp_sum(dx * dx + dy * dy + dz * dz + dw * dw) * (1.f / 128.f);
            float rstd = rsqrtf(var + 1e-5f);
            int row = row0 + r;
            if (row < nrows) {
                *(float4*)&out[(size_t)row * 128 + lane * 4] =
                    make_float4(fmaxf(dx * rstd * gB.x + bB.x, 0.f),
                                fmaxf(dy * rstd * gB.y + bB.y, 0.f),
                                fmaxf(dz * rstd * gB.z + bB.z, 0.f),
                                fmaxf(dw * rstd * gB.w + bB.w, 0.f));
            }
        }
        __syncthreads();
    }
}

// ---------------------------------------------------------------------------
extern "C" void kernel_launch(void* const* d_in, const int* in_sizes, int n_in,
                              void* d_out, int out_size) {
    const int N = in_sizes[0] / IN_DIM;
    const int E = in_sizes[1];
    const int M = out_size / IN_DIM - N;

    const int wi = n_in - 18;
    const float* x0 = (const float*)d_in[0];
    const int* node_idx  = (const int*)d_in[1];
    const int* hedge_idx = (const int*)d_in[2];
    const float* w[18];
    for (int i = 0; i < 18; i++) w[i] = (const float*)d_in[wi + i];

    float* out = (float*)d_out;            // x_0_out [N,128]
    float* x1  = out + (size_t)N * IN_DIM; // x_1     [M,128]

    const int gemmSmem = (128 * SW + 128 * SA + 544) * 4;   // ~139.9 KB
    const int mlpSmem  = (256 * SW + 128 * SA) * 4;         // ~206.8 KB

    static int s_init = 0;
    static cudaStream_t s2;
    static cudaEvent_t evFork, evA, evB;
    static void *cnt_ptr, *offA_ptr, *offB_ptr, *esrcA_ptr, *esrcB_ptr;
    if (!s_init) {
        cudaFuncSetAttribute(gemm_xv,
                             cudaFuncAttributeMaxDynamicSharedMemorySize, gemmSmem);
        cudaFuncSetAttribute(mlp_kernel,
                             cudaFuncAttributeMaxDynamicSharedMemorySize, mlpSmem);
        cudaStreamCreateWithFlags(&s2, cudaStreamNonBlocking);
        cudaEventCreateWithFlags(&evFork, cudaEventDisableTiming);
        cudaEventCreateWithFlags(&evA, cudaEventDisableTiming);
        cudaEventCreateWithFlags(&evB, cudaEventDisableTiming);
        cudaGetSymbolAddress(&cnt_ptr, g_cnt);
        cudaGetSymbolAddress(&offA_ptr, g_offA);
        cudaGetSymbolAddress(&offB_ptr, g_offB);
        cudaGetSymbolAddress(&esrcA_ptr, g_esrcA);
        cudaGetSymbolAddress(&esrcB_ptr, g_esrcB);
        s_init = 1;
    }
    int* offA = (int*)offA_ptr;
    int* offB = (int*)offB_ptr;
    int* esrcA = (int*)esrcA_ptr;
    int* esrcB = (int*)esrcB_ptr;

    const int nbM = (M + 1023) / 1024, nbN = (N + 1023) / 1024;
    const int xvTilesN = (N + 127) / 128, xvTilesM = (M + 127) / 128;
    const int mlpTilesN = (N + 63) / 64, mlpTilesM = (M + 63) / 64;
    const int PGRID = 148;
    auto mini = [](int a, int b) { return a < b ? a : b; };

    cudaEventRecord(evFork, 0);
    cudaStreamWaitEvent(s2, evFork, 0);

    // s2: CSR A (targets = hyperedges)   [launches 1-4]
    cudaMemsetAsync(cnt_ptr, 0, sizeof(int) * (M + 1), s2);
    hist_kernel<<<512, 256, 0, s2>>>(hedge_idx, E);
    scan_kernel<<<nbM, 1024, 0, s2>>>(M, offA);
    scatter_kernel<<<512, 256, 0, s2>>>(hedge_idx, node_idx, esrcA, E);
    cudaEventRecord(evA, s2);

    // stream 0: phase 1 (v2e)           [launch 5 = gemm_xv, 6 = segagg]
    gemm_xv<<<mini(PGRID, xvTilesN), 256, gemmSmem>>>(x0, w[2], w[0], w[1],
                                                      N, xvTilesN);
    cudaStreamWaitEvent(0, evA, 0);
    segagg_kernel<<<(M + 7) / 8, 256>>>(esrcA, offA, w[1], M);
    mlp_kernel<<<mini(PGRID, mlpTilesM), 256, mlpSmem>>>(w[3], w[4], w[5], w[6],
                                                         w[7], w[8], x1, M,
                                                         mlpTilesM);

    // s2: CSR B (targets = nodes) — runs right after CSR A, overlaps phase 1
    cudaMemsetAsync(cnt_ptr, 0, sizeof(int) * (N + 1), s2);
    hist_kernel<<<512, 256, 0, s2>>>(node_idx, E);
    scan_kernel<<<nbN, 1024, 0, s2>>>(N, offB);
    scatter_kernel<<<512, 256, 0, s2>>>(node_idx, hedge_idx, esrcB, E);
    cudaEventRecord(evB, s2);

    // stream 0: phase 2 (e2v)
    gemm_xv<<<mini(PGRID, xvTilesM), 256, gemmSmem>>>(x1, w[11], w[9], w[10],
                                                      M, xvTilesM);
    cudaStreamWaitEvent(0, evB, 0);
    segagg_kernel<<<(N + 7) / 8, 256>>>(esrcB, offB, w[10], N);
    mlp_kernel<<<mini(PGRID, mlpTilesN), 256, mlpSmem>>>(w[12], w[13], w[14],
                                                         w[15], w[16], w[17],
                                                         out, N, mlpTilesN);
}

// round 11
// speedup vs baseline: 1.4737x; 1.0288x over previous
#include <cuda_runtime.h>
#include <math.h>
#include <stdint.h>

#define IN_DIM 128
#define NHEAD 4
#define HDIM 32
#define MAX_ROWS 51200
#define MAX_E 1050000
#define SA 132   // smem stride activation tiles
#define SW 136   // smem stride weight tiles

__device__ __align__(16) float g_p[MAX_ROWS * NHEAD];    // [n][h] p = exp(alpha)
__device__ __align__(16) float g_xv[MAX_ROWS * IN_DIM];  // [n][d*4+h]
__device__ __align__(16) float g_S1[MAX_ROWS * IN_DIM];  // pre-MLP features
__device__ int g_esrcA[MAX_E];
__device__ int g_esrcB[MAX_E];
__device__ int g_offA[MAX_ROWS + 1];
__device__ int g_offB[MAX_ROWS + 1];
__device__ int g_cnt[MAX_ROWS + 1];
__device__ int g_cur[MAX_ROWS + 1];
__device__ int g_scst[64];                 // lookback states

__device__ __forceinline__ float warp_sum(float v) {
    #pragma unroll
    for (int off = 16; off; off >>= 1) v += __shfl_xor_sync(0xffffffffu, v, off);
    return v;
}

__device__ __forceinline__ float to_tf32(float x) {
    uint32_t u;
    asm("cvt.rna.tf32.f32 %0, %1;" : "=r"(u) : "f"(x));
    return __uint_as_float(u);
}

__device__ __forceinline__ void mma_tile(float c[4], const uint32_t a[4],
                                         uint32_t b0, uint32_t b1) {
    asm volatile(
        "mma.sync.aligned.m16n8k8.row.col.f32.tf32.tf32.f32 "
        "{%0,%1,%2,%3}, {%4,%5,%6,%7}, {%8,%9}, {%0,%1,%2,%3};"
        : "+f"(c[0]), "+f"(c[1]), "+f"(c[2]), "+f"(c[3])
        : "r"(a[0]), "r"(a[1]), "r"(a[2]), "r"(a[3]), "r"(b0), "r"(b1));
}

// warp computes 32 rows x 32 cols (2 m-frags x 4 n-frags)
__device__ __forceinline__ void gemm_core_32x32(const float* __restrict__ shA,
                                                const float* __restrict__ shB,
                                                float acc[2][4][4],
                                                int rowbase, int colbase, int lane) {
    int g = lane >> 2, t = lane & 3;
    #pragma unroll 2
    for (int k0 = 0; k0 < 128; k0 += 8) {
        uint32_t a[2][4];
        #pragma unroll
        for (int mi = 0; mi < 2; mi++) {
            const float* p = shA + (rowbase + mi * 16 + g) * SA + k0 + t;
            a[mi][0] = __float_as_uint(p[0]);
            a[mi][1] = __float_as_uint(p[8 * SA]);
            a[mi][2] = __float_as_uint(p[4]);
            a[mi][3] = __float_as_uint(p[8 * SA + 4]);
        }
        #pragma unroll
        for (int ni = 0; ni < 4; ni++) {
            const float* q = shB + (k0 + t) * SW + colbase + ni * 8 + g;
            uint32_t b0 = __float_as_uint(q[0]);
            uint32_t b1 = __float_as_uint(q[4 * SW]);
            mma_tile(acc[0][ni], a[0], b0, b1);
            mma_tile(acc[1][ni], a[1], b0, b1);
        }
    }
}

// warp computes 32 rows x 16 cols (2 m-frags x 2 n-frags)
__device__ __forceinline__ void gemm_core_32x16(const float* __restrict__ shA,
                                                const float* __restrict__ shB,
                                                float acc[2][2][4],
                                                int rowbase, int colbase, int lane) {
    int g = lane >> 2, t = lane & 3;
    #pragma unroll 2
    for (int k0 = 0; k0 < 128; k0 += 8) {
        uint32_t a[2][4];
        #pragma unroll
        for (int mi = 0; mi < 2; mi++) {
            const float* p = shA + (rowbase + mi * 16 + g) * SA + k0 + t;
            a[mi][0] = __float_as_uint(p[0]);
            a[mi][1] = __float_as_uint(p[8 * SA]);
            a[mi][2] = __float_as_uint(p[4]);
            a[mi][3] = __float_as_uint(p[8 * SA + 4]);
        }
        #pragma unroll
        for (int ni = 0; ni < 2; ni++) {
            const float* q = shB + (k0 + t) * SW + colbase + ni * 8 + g;
            uint32_t b0 = __float_as_uint(q[0]);
            uint32_t b1 = __float_as_uint(q[4 * SW]);
            mma_tile(acc[0][ni], a[0], b0, b1);
            mma_tile(acc[1][ni], a[1], b0, b1);
        }
    }
}

// ---------------------------------------------------------------------------
// Persistent, 512 threads: V + kq resident; loop over 128-row tiles.
// Per tile: xv = x@V_cat (tf32 MMA), p = exp(x . kq) from the smem x tile.
__global__ void __launch_bounds__(512, 1)
gemm_xv(const float* __restrict__ x, const float* __restrict__ V,
        const float* __restrict__ K, const float* __restrict__ Q,
        int nrows, int ntiles) {
    extern __shared__ float sm[];
    float* ws = sm;                         // [c][d*4+h], stride SW
    float* xs = sm + 128 * SW;              // [r][c], stride SA (also C staging)
    float* kq_s = sm + 128 * SW + 128 * SA; // [h*132 + c]
    int tid = threadIdx.x;
    int lane = tid & 31, wid = tid >> 5;    // 16 warps
    int wm = wid & 3, wn = wid >> 2;        // 32-row x 32-col warp tile
    int rowbase = wm * 32, colbase = wn * 32;
    int g = lane >> 2, t = lane & 3;

    // one-time: kq + V (permuted, tf32)
    {
        int h = tid >> 7, c = tid & 127;
        float s = 0.f;
        #pragma unroll
        for (int d = 0; d < HDIM; d++)
            s += K[h * (IN_DIM * HDIM) + c * HDIM + d] * Q[h * HDIM + d];
        kq_s[h * 132 + c] = s;
    }
    for (int idx = tid; idx < 16384; idx += 512) {   // V linear: h,c,d
        int h = idx >> 12, c = (idx >> 5) & 127, d = idx & 31;
        ws[c * SW + d * 4 + h] = to_tf32(V[idx]);
    }
    __syncthreads();

    for (int tile = blockIdx.x; tile < ntiles; tile += gridDim.x) {
        int row0 = tile * 128;
        for (int idx = tid; idx < 4096; idx += 512) {
            int r = idx >> 5, q = idx & 31;
            int row = row0 + r;
            float4 v = (row < nrows) ? *(const float4*)&x[(size_t)row * 128 + q * 4]
                                     : make_float4(0.f, 0.f, 0.f, 0.f);
            xs[r * SA + q * 4 + 0] = to_tf32(v.x);
            xs[r * SA + q * 4 + 1] = to_tf32(v.y);
            xs[r * SA + q * 4 + 2] = to_tf32(v.z);
            xs[r * SA + q * 4 + 3] = to_tf32(v.w);
        }
        __syncthreads();

        float acc[2][4][4];
        #pragma unroll
        for (int i = 0; i < 2; i++)
            #pragma unroll
            for (int j = 0; j < 4; j++)
                #pragma unroll
                for (int k = 0; k < 4; k++) acc[i][j][k] = 0.f;
        gemm_core_32x32(xs, ws, acc, rowbase, colbase, lane);

        // p = exp(x . kq): 512 tasks, 1 per thread, float4 LDS
        {
            int r = tid >> 2, h = tid & 3;
            const float4* xr4 = (const float4*)&xs[r * SA];
            const float4* kr4 = (const float4*)&kq_s[h * 132];
            float s = 0.f;
            #pragma unroll 8
            for (int c = 0; c < 32; c++) {
                float4 xv4 = xr4[c], kv4 = kr4[c];
                s += xv4.x * kv4.x + xv4.y * kv4.y + xv4.z * kv4.z + xv4.w * kv4.w;
            }
            int row = row0 + r;
            if (row < nrows) g_p[(size_t)row * 4 + h] = __expf(s);
        }
        __syncthreads();

        #pragma unroll
        for (int mi = 0; mi < 2; mi++)
            #pragma unroll
            for (int ni = 0; ni < 4; ni++) {
                int r = rowbase + mi * 16 + g;
                int c = colbase + ni * 8 + 2 * t;
                *(float2*)&xs[r * SA + c] = make_float2(acc[mi][ni][0], acc[mi][ni][1]);
                *(float2*)&xs[(r + 8) * SA + c] = make_float2(acc[mi][ni][2], acc[mi][ni][3]);
            }
        __syncthreads();

        for (int idx = tid; idx < 4096; idx += 512) {
            int r = idx >> 5, q = idx & 31;
            int row = row0 + r;
            if (row < nrows)
                *(float4*)&g_xv[(size_t)row * 128 + q * 4] = *(float4*)&xs[r * SA + q * 4];
        }
        __syncthreads();
    }
}

// ---------------------------------------------------------------------------
__global__ void hist_kernel(const int* __restrict__ tgt, int E) {
    if (blockIdx.x == 0 && threadIdx.x < 64) g_scst[threadIdx.x] = 0;
    int stride = gridDim.x * blockDim.x;
    int gid = blockIdx.x * blockDim.x + threadIdx.x;
    int n4 = E >> 2;
    const int4* t4 = (const int4*)tgt;
    for (int i = gid; i < n4; i += stride) {
        int4 t = t4[i];
        atomicAdd(&g_cnt[t.x], 1);
        atomicAdd(&g_cnt[t.y], 1);
        atomicAdd(&g_cnt[t.z], 1);
        atomicAdd(&g_cnt[t.w], 1);
    }
    for (int e = n4 * 4 + gid; e < E; e += stride) atomicAdd(&g_cnt[tgt[e]], 1);
}

// single-launch exclusive scan, decoupled lookback (grid <= 50 blocks)
__global__ void scan_kernel(int n, int* __restrict__ off) {
    __shared__ int wsum[32];
    __shared__ int s_excl;
    int tid = threadIdx.x, lane = tid & 31, wid = tid >> 5;
    int bid = blockIdx.x;
    int i = bid * 1024 + tid;
    int v = (i < n) ? g_cnt[i] : 0;
    int x = v;
    #pragma unroll
    for (int o = 1; o < 32; o <<= 1) {
        int t = __shfl_up_sync(0xffffffffu, x, o);
        if (lane >= o) x += t;
    }
    if (lane == 31) wsum[wid] = x;
    __syncthreads();
    if (wid == 0) {
        int s = wsum[lane];
        #pragma unroll
        for (int o = 1; o < 32; o <<= 1) {
            int t = __shfl_up_sync(0xffffffffu, s, o);
            if (lane >= o) s += t;
        }
        wsum[lane] = s;
    }
    __syncthreads();
    int base = (wid > 0) ? wsum[wid - 1] : 0;
    int incl = base + x;
    int local_total = wsum[31];

    if (tid == 0) {
        int run = 0;
        if (bid > 0) {
            atomicExch(&g_scst[bid], (local_total << 2) | 1);
            int j = bid - 1;
            while (j >= 0) {
                int st = atomicAdd(&g_scst[j], 0);
                int tag = st & 3;
                if (tag == 2) { run += st >> 2; break; }
                if (tag == 1) { run += st >> 2; j--; }
            }
        }
        atomicExch(&g_scst[bid], ((run + local_total) << 2) | 2);
        s_excl = run;
    }
    __syncthreads();
    int e = s_excl + incl - v;
    if (i < n) { off[i] = e; g_cur[i] = e; }
    if (bid == gridDim.x - 1 && tid == 1023) off[n] = s_excl + local_total;
}

__global__ void scatter_kernel(const int* __restrict__ tgt,
                               const int* __restrict__ src,
                               int* __restrict__ esrc, int E) {
    int stride = gridDim.x * blockDim.x;
    int gid = blockIdx.x * blockDim.x + threadIdx.x;
    int n4 = E >> 2;
    const int4* t4 = (const int4*)tgt;
    const int4* s4 = (const int4*)src;
    for (int i = gid; i < n4; i += stride) {
        int4 t = t4[i]; int4 s = s4[i];
        int p;
        p = atomicAdd(&g_cur[t.x], 1); esrc[p] = s.x;
        p = atomicAdd(&g_cur[t.y], 1); esrc[p] = s.y;
        p = atomicAdd(&g_cur[t.z], 1); esrc[p] = s.z;
        p = atomicAdd(&g_cur[t.w], 1); esrc[p] = s.w;
    }
    for (int e = n4 * 4 + gid; e < E; e += stride) {
        int p = atomicAdd(&g_cur[tgt[e]], 1); esrc[p] = src[e];
    }
}

// ---------------------------------------------------------------------------
// Single pass: acc += p_j * v_j, s += p_j; out = acc/s + bias.
__global__ void __launch_bounds__(256)
segagg_kernel(const int* __restrict__ esrc, const int* __restrict__ off,
              const float* __restrict__ qbias, int n_tgt) {
    __shared__ int    sh_sn[256];
    __shared__ float4 sh_p[256];
    int wid = threadIdx.x >> 5, lane = threadIdx.x & 31;
    int gw = blockIdx.x * 8 + wid;
    if (gw >= n_tgt) return;
    int start = off[gw], end = off[gw + 1];
    float* outrow = &g_S1[(size_t)gw * 128];

    if (end == start) {
        #pragma unroll
        for (int k = 0; k < 4; k++) outrow[k * 32 + lane] = qbias[k * 32 + lane];
        return;
    }

    int sbase = wid * 32;
    float acc[4] = {0.f, 0.f, 0.f, 0.f};
    float4 sacc = make_float4(0.f, 0.f, 0.f, 0.f);
    for (int i0 = start; i0 < end; i0 += 32) {
        int cnt = end - i0; if (cnt > 32) cnt = 32;
        if (lane < cnt) {
            int sn = __ldg(&esrc[i0 + lane]);
            float4 p4 = *(const float4*)&g_p[(size_t)sn * 4];
            sh_sn[sbase + lane] = sn;
            sh_p[sbase + lane] = p4;
            sacc.x += p4.x; sacc.y += p4.y; sacc.z += p4.z; sacc.w += p4.w;
        }
        __syncwarp();
        #pragma unroll 4
        for (int j = 0; j < cnt; j++) {
            int sn = sh_sn[sbase + j];
            float4 pv = sh_p[sbase + j];
            float4 v = *(const float4*)&g_xv[(size_t)sn * 128 + lane * 4];
            acc[0] += pv.x * v.x; acc[1] += pv.y * v.y;
            acc[2] += pv.z * v.z; acc[3] += pv.w * v.w;
        }
        __syncwarp();
    }
    float inv0 = 1.0f / warp_sum(sacc.x);
    float inv1 = 1.0f / warp_sum(sacc.y);
    float inv2 = 1.0f / warp_sum(sacc.z);
    float inv3 = 1.0f / warp_sum(sacc.w);
    outrow[lane]      = acc[0] * inv0 + qbias[lane];
    outrow[32 + lane] = acc[1] * inv1 + qbias[32 + lane];
    outrow[64 + lane] = acc[2] * inv2 + qbias[64 + lane];
    outrow[96 + lane] = acc[3] * inv3 + qbias[96 + lane];
}

// ---------------------------------------------------------------------------
// Persistent MLP, 512 threads: W1+W2 resident, loop over 64-row tiles.
// LN0 -> relu(h@W1) -> relu(t@W2) -> residual -> LN1 -> relu.
__global__ void __launch_bounds__(512, 1)
mlp_kernel(const float* __restrict__ g0, const float* __restrict__ b0,
           const float* __restrict__ W1, const float* __restrict__ W2,
           const float* __restrict__ g1, const float* __restrict__ b1,
           float* __restrict__ out, int nrows, int ntiles) {
    extern __shared__ float sm[];
    float* sh_w1 = sm;                      // [128][SW]
    float* sh_w2 = sm + 128 * SW;           // [128][SW]
    float* sh_h  = sm + 256 * SW;           // [64][SA]
    float* sh_t  = sm + 256 * SW + 64 * SA; // [64][SA]
    int tid = threadIdx.x;
    int wid = tid >> 5, lane = tid & 31;    // 16 warps
    int wm = wid & 1, wn = wid >> 1;        // 32-row x 16-col warp tile
    int rowbase = wm * 32, colbase = wn * 16;
    int g = lane >> 2, t = lane & 3;

    for (int idx = tid; idx < 4096; idx += 512) {
        float4 v1 = *(const float4*)&W1[idx * 4];
        float4 v2 = *(const float4*)&W2[idx * 4];
        int r = idx >> 5, q = idx & 31;
        sh_w1[r * SW + q * 4 + 0] = to_tf32(v1.x);
        sh_w1[r * SW + q * 4 + 1] = to_tf32(v1.y);
        sh_w1[r * SW + q * 4 + 2] = to_tf32(v1.z);
        sh_w1[r * SW + q * 4 + 3] = to_tf32(v1.w);
        sh_w2[r * SW + q * 4 + 0] = to_tf32(v2.x);
        sh_w2[r * SW + q * 4 + 1] = to_tf32(v2.y);
        sh_w2[r * SW + q * 4 + 2] = to_tf32(v2.z);
        sh_w2[r * SW + q * 4 + 3] = to_tf32(v2.w);
    }
    float4 gA = *(const float4*)&g0[lane * 4];
    float4 bA = *(const float4*)&b0[lane * 4];
    float4 gB = *(const float4*)&g1[lane * 4];
    float4 bB = *(const float4*)&b1[lane * 4];
    __syncthreads();

    for (int tile = blockIdx.x; tile < ntiles; tile += gridDim.x) {
        int row0 = tile * 64;
        for (int idx = tid; idx < 2048; idx += 512) {
            int r = idx >> 5, q = idx & 31;
            int row = row0 + r;
            float4 v = (row < nrows) ? *(const float4*)&g_S1[(size_t)row * 128 + q * 4]
                                     : make_float4(0.f, 0.f, 0.f, 0.f);
            *(float4*)&sh_h[r * SA + q * 4] = v;
        }
        __syncthreads();

        // LN0 in place (tf32 out)
        for (int r = wid; r < 64; r += 16) {
            float4 v = *(float4*)&sh_h[r * SA + lane * 4];
            float mean = warp_sum(v.x + v.y + v.z + v.w) * (1.f / 128.f);
            float dx = v.x - mean, dy = v.y - mean, dz = v.z - mean, dw = v.w - mean;
            float var = warp_sum(dx * dx + dy * dy + dz * dz + dw * dw) * (1.f / 128.f);
            float rstd = rsqrtf(var + 1e-5f);
            sh_h[r * SA + lane * 4 + 0] = to_tf32(dx * rstd * gA.x + bA.x);
            sh_h[r * SA + lane * 4 + 1] = to_tf32(dy * rstd * gA.y + bA.y);
            sh_h[r * SA + lane * 4 + 2] = to_tf32(dz * rstd * gA.z + bA.z);
            sh_h[r * SA + lane * 4 + 3] = to_tf32(dw * rstd * gA.w + bA.w);
        }
        __syncthreads();

        float acc[2][2][4];
        #pragma unroll
        for (int i = 0; i < 2; i++)
            #pragma unroll
            for (int j = 0; j < 2; j++)
                #pragma unroll
                for (int k = 0; k < 4; k++) acc[i][j][k] = 0.f;
        gemm_core_32x16(sh_h, sh_w1, acc, rowbase, colbase, lane);

        // residual h at this thread's C positions
        float hres[2][2][4];
        #pragma unroll
        for (int mi = 0; mi < 2; mi++)
            #pragma unroll
            for (int ni = 0; ni < 2; ni++) {
                int r = rowbase + mi * 16 + g;
                int c = colbase + ni * 8 + 2 * t;
                hres[mi][ni][0] = sh_h[r * SA + c];
                hres[mi][ni][1] = sh_h[r * SA + c + 1];
                hres[mi][ni][2] = sh_h[(r + 8) * SA + c];
                hres[mi][ni][3] = sh_h[(r + 8) * SA + c + 1];
            }
        // t = relu(acc) tf32 -> sh_t
        #pragma unroll
        for (int mi = 0; mi < 2; mi++)
            #pragma unroll
            for (int ni = 0; ni < 2; ni++) {
                int r = rowbase + mi * 16 + g;
                int c = colbase + ni * 8 + 2 * t;
                sh_t[r * SA + c]           = to_tf32(fmaxf(acc[mi][ni][0], 0.f));
                sh_t[r * SA + c + 1]       = to_tf32(fmaxf(acc[mi][ni][1], 0.f));
                sh_t[(r + 8) * SA + c]     = to_tf32(fmaxf(acc[mi][ni][2], 0.f));
                sh_t[(r + 8) * SA + c + 1] = to_tf32(fmaxf(acc[mi][ni][3], 0.f));
            }
        __syncthreads();

        #pragma unroll
        for (int i = 0; i < 2; i++)
            #pragma unroll
            for (int j = 0; j < 2; j++)
                #pragma unroll
                for (int k = 0; k < 4; k++) acc[i][j][k] = 0.f;
        gemm_core_32x16(sh_t, sh_w2, acc, rowbase, colbase, lane);
        __syncthreads();   // all sh_t reads done

        #pragma unroll
        for (int mi = 0; mi < 2; mi++)
            #pragma unroll
            for (int ni = 0; ni < 2; ni++) {
                int r = rowbase + mi * 16 + g;
                int c = colbase + ni * 8 + 2 * t;
                sh_t[r * SA + c]           = hres[mi][ni][0] + fmaxf(acc[mi][ni][0], 0.f);
                sh_t[r * SA + c + 1]       = hres[mi][ni][1] + fmaxf(acc[mi][ni][1], 0.f);
                sh_t[(r + 8) * SA + c]     = hres[mi][ni][2] + fmaxf(acc[mi][ni][2], 0.f);
                sh_t[(r + 8) * SA + c + 1] = hres[mi][ni][3] + fmaxf(acc[mi][ni][3], 0.f);
            }
        __syncthreads();

        for (int r = wid; r < 64; r += 16) {
            float4 v = *(float4*)&sh_t[r * SA + lane * 4];
            float mean = warp_sum(v.x + v.y + v.z + v.w) * (1.f / 128.f);
            float dx = v.x - mean, dy = v.y - mean, dz = v.z - mean, dw = v.w - mean;
            float var = warp_sum(dx * dx + dy * dy + dz * dz + dw * dw) * (1.f / 128.f);
            float rstd = rsqrtf(var + 1e-5f);
            int row = row0 + r;
            if (row < nrows) {
                *(float4*)&out[(size_t)row * 128 + lane * 4] =
                    make_float4(fmaxf(dx * rstd * gB.x + bB.x, 0.f),
                                fmaxf(dy * rstd * gB.y + bB.y, 0.f),
                                fmaxf(dz * rstd * gB.z + bB.z, 0.f),
                                fmaxf(dw * rstd * gB.w + bB.w, 0.f));
            }
        }
        __syncthreads();
    }
}

// ---------------------------------------------------------------------------
extern "C" void kernel_launch(void* const* d_in, const int* in_sizes, int n_in,
                              void* d_out, int out_size) {
    const int N = in_sizes[0] / IN_DIM;
    const int E = in_sizes[1];
    const int M = out_size / IN_DIM - N;

    const int wi = n_in - 18;
    const float* x0 = (const float*)d_in[0];
    const int* node_idx  = (const int*)d_in[1];
    const int* hedge_idx = (const int*)d_in[2];
    const float* w[18];
    for (int i = 0; i < 18; i++) w[i] = (const float*)d_in[wi + i];

    float* out = (float*)d_out;            // x_0_out [N,128]
    float* x1  = out + (size_t)N * IN_DIM; // x_1     [M,128]

    const int gemmSmem = (128 * SW + 128 * SA + 544) * 4;   // ~139.9 KB
    const int mlpSmem  = (256 * SW + 128 * SA) * 4;         // ~206.8 KB

    static int s_init = 0;
    static cudaStream_t s2;
    static cudaEvent_t evFork, evA, evB;
    static void *cnt_ptr, *offA_ptr, *offB_ptr, *esrcA_ptr, *esrcB_ptr;
    if (!s_init) {
        cudaFuncSetAttribute(gemm_xv,
                             cudaFuncAttributeMaxDynamicSharedMemorySize, gemmSmem);
        cudaFuncSetAttribute(mlp_kernel,
                             cudaFuncAttributeMaxDynamicSharedMemorySize, mlpSmem);
        cudaStreamCreateWithFlags(&s2, cudaStreamNonBlocking);
        cudaEventCreateWithFlags(&evFork, cudaEventDisableTiming);
        cudaEventCreateWithFlags(&evA, cudaEventDisableTiming);
        cudaEventCreateWithFlags(&evB, cudaEventDisableTiming);
        cudaGetSymbolAddress(&cnt_ptr, g_cnt);
        cudaGetSymbolAddress(&offA_ptr, g_offA);
        cudaGetSymbolAddress(&offB_ptr, g_offB);
        cudaGetSymbolAddress(&esrcA_ptr, g_esrcA);
        cudaGetSymbolAddress(&esrcB_ptr, g_esrcB);
        s_init = 1;
    }
    int* offA = (int*)offA_ptr;
    int* offB = (int*)offB_ptr;
    int* esrcA = (int*)esrcA_ptr;
    int* esrcB = (int*)esrcB_ptr;

    const int nbM = (M + 1023) / 1024, nbN = (N + 1023) / 1024;
    const int xvTilesN = (N + 127) / 128, xvTilesM = (M + 127) / 128;
    const int mlpTilesN = (N + 63) / 64, mlpTilesM = (M + 63) / 64;
    const int PGRID = 148;
    auto mini = [](int a, int b) { return a < b ? a : b; };

    cudaEventRecord(evFork, 0);
    cudaStreamWaitEvent(s2, evFork, 0);

    // s2: CSR A (targets = hyperedges)
    cudaMemsetAsync(cnt_ptr, 0, sizeof(int) * (M + 1), s2);
    hist_kernel<<<512, 256, 0, s2>>>(hedge_idx, E);
    scan_kernel<<<nbM, 1024, 0, s2>>>(M, offA);
    scatter_kernel<<<512, 256, 0, s2>>>(hedge_idx, node_idx, esrcA, E);
    cudaEventRecord(evA, s2);

    // stream 0: phase 1 (v2e)
    gemm_xv<<<mini(PGRID, xvTilesN), 512, gemmSmem>>>(x0, w[2], w[0], w[1],
                                                      N, xvTilesN);
    cudaStreamWaitEvent(0, evA, 0);
    segagg_kernel<<<(M + 7) / 8, 256>>>(esrcA, offA, w[1], M);
    mlp_kernel<<<mini(PGRID, mlpTilesM), 512, mlpSmem>>>(w[3], w[4], w[5], w[6],
                                                         w[7], w[8], x1, M,
                                                         mlpTilesM);

    // s2: CSR B (targets = nodes) — overlaps phase 1
    cudaMemsetAsync(cnt_ptr, 0, sizeof(int) * (N + 1), s2);
    hist_kernel<<<512, 256, 0, s2>>>(node_idx, E);
    scan_kernel<<<nbN, 1024, 0, s2>>>(N, offB);
    scatter_kernel<<<512, 256, 0, s2>>>(node_idx, hedge_idx, esrcB, E);
    cudaEventRecord(evB, s2);

    // stream 0: phase 2 (e2v)
    gemm_xv<<<mini(PGRID, xvTilesM), 512, gemmSmem>>>(x1, w[11], w[9], w[10],
                                                      M, xvTilesM);
    cudaStreamWaitEvent(0, evB, 0);
    segagg_kernel<<<(N + 7) / 8, 256>>>(esrcB, offB, w[10], N);
    mlp_kernel<<<mini(PGRID, mlpTilesN), 512, mlpSmem>>>(w[12], w[13], w[14],
                                                         w[15], w[16], w[17],
                                                         out, N, mlpTilesN);
}